// round 8
// baseline (speedup 1.0000x reference)
#include <cuda_runtime.h>
#include <cuda_bf16.h>
#include <stdint.h>
#include <math.h>

#define B_  16
#define C_  1024
#define CH_ 512
#define HW_ 4096

// ---------------- device scratch ----------------
__device__ __align__(16) __nv_bfloat16 g_wbf[1536 * 1024];              // stacked [ql;vr;vl] bf16
__device__ __align__(16) __nv_bfloat16 g_xbf[(size_t)B_ * HW_ * 1024];  // xT[b][n][k] bf16
__device__ __align__(16) float g_qrp[B_ * 8 * HW_];  // qr partials per 128-channel block
__device__ __align__(16) float g_mask[B_ * HW_];
__device__ __align__(16) float g_avg[B_ * CH_];
__device__ __align__(16) float g_spatial[B_ * CH_];
__device__ __align__(16) float g_chattn[B_ * HW_];
__device__ __align__(16) float g_part_m[B_ * 8 * 32 * 128];  // (b, mtile8, ntile32, row128)
__device__ __align__(16) float g_part_n[B_ * 32 * 4 * 128];  // (b, ntile32, mtile4, col128)

// ---------------- helpers ----------------
__device__ __forceinline__ uint32_t s2u(const void* p) {
    uint32_t a;
    asm("{ .reg .u64 t; cvta.to.shared.u64 t, %1; cvt.u32.u64 %0, t; }" : "=r"(a) : "l"(p));
    return a;
}
__device__ __forceinline__ void cp16(uint32_t dst, const void* src) {
    asm volatile("cp.async.cg.shared.global [%0], [%1], 16;" :: "r"(dst), "l"(src) : "memory");
}
#define CP_COMMIT() asm volatile("cp.async.commit_group;" ::: "memory")
#define CP_WAIT(n)  asm volatile("cp.async.wait_group %0;" :: "n"(n) : "memory")

__device__ __forceinline__ void ldsm4(uint32_t* r, uint32_t addr) {
    asm volatile("ldmatrix.sync.aligned.m8n8.x4.shared.b16 {%0,%1,%2,%3}, [%4];"
                 : "=r"(r[0]), "=r"(r[1]), "=r"(r[2]), "=r"(r[3]) : "r"(addr));
}

__device__ __forceinline__ void mma16816(float* d, uint32_t a0, uint32_t a1, uint32_t a2,
                                         uint32_t a3, uint32_t b0, uint32_t b1) {
    asm volatile(
        "mma.sync.aligned.m16n8k16.row.col.f32.bf16.bf16.f32 "
        "{%0,%1,%2,%3}, {%4,%5,%6,%7}, {%8,%9}, {%0,%1,%2,%3};"
        : "+f"(d[0]), "+f"(d[1]), "+f"(d[2]), "+f"(d[3])
        : "r"(a0), "r"(a1), "r"(a2), "r"(a3), "r"(b0), "r"(b1));
}

// ---------------- conversion kernels ----------------
__global__ void convert_w(const float* __restrict__ wql, const float* __restrict__ wvr,
                          const float* __restrict__ wvl) {
    const int i = blockIdx.x * 512 + threadIdx.x;  // 786432 pairs
    const int m = i >> 9;
    const int k = (i & 511) * 2;
    const float* src = (m < 512) ? (wql + (size_t)m * 1024)
                                 : ((m < 1024) ? (wvr + (size_t)(m - 512) * 1024)
                                               : (wvl + (size_t)(m - 1024) * 1024));
    __nv_bfloat162 h = __floats2bfloat162_rn(src[k], src[k + 1]);
    ((uint32_t*)g_wbf)[i] = *reinterpret_cast<uint32_t*>(&h);
}

// x[b][c][n] fp32 -> xT[b][n][c] bf16, plus fused partial qr dot product.
__global__ void transpose_x(const float* __restrict__ x, const float* __restrict__ wqr) {
    __shared__ float s[32][129];
    const int tid = threadIdx.x;
    const int n0 = blockIdx.x * 32, c0 = blockIdx.y * 128, b = blockIdx.z;
#pragma unroll
    for (int r = 0; r < 16; r++) {
        const int ci = (tid >> 5) + r * 8;
        const int ni = tid & 31;
        s[ni][ci] = x[((size_t)(b * C_ + c0 + ci)) * HW_ + n0 + ni];
    }
    __syncthreads();
#pragma unroll
    for (int r = 0; r < 8; r++) {
        const int ni = (tid >> 6) + r * 4;
        const int u = tid & 63;
        __nv_bfloat162 h = __floats2bfloat162_rn(s[ni][u * 2], s[ni][u * 2 + 1]);
        ((uint32_t*)g_xbf)[((size_t)(b * HW_ + n0 + ni)) * 512 + (c0 >> 1) + u] =
            *reinterpret_cast<uint32_t*>(&h);
    }
    {
        const int ni = tid >> 3, lg = tid & 7;
        float p = 0.f;
#pragma unroll
        for (int r = 0; r < 16; r++) {
            const int ci = lg * 16 + r;
            p = fmaf(wqr[c0 + ci], s[ni][ci], p);
        }
#pragma unroll
        for (int o = 1; o <= 4; o <<= 1) p += __shfl_xor_sync(0xffffffffu, p, o);
        if (lg == 0) g_qrp[((size_t)b * 8 + blockIdx.y) * HW_ + n0 + ni] = p;
    }
}

// ---------------- small reductions ----------------
template <int NW>
__device__ __forceinline__ float blockSum(float v, float* sh, float* bc) {
#pragma unroll
    for (int o = 16; o > 0; o >>= 1) v += __shfl_xor_sync(0xffffffffu, v, o);
    int t = threadIdx.x;
    if ((t & 31) == 0) sh[t >> 5] = v;
    __syncthreads();
    if (t < 32) {
        float w = (t < NW) ? sh[t] : 0.f;
#pragma unroll
        for (int o = 16; o > 0; o >>= 1) w += __shfl_xor_sync(0xffffffffu, w, o);
        if (t == 0) *bc = w;
    }
    __syncthreads();
    return *bc;
}
template <int NW>
__device__ __forceinline__ float blockMax(float v, float* sh, float* bc) {
#pragma unroll
    for (int o = 16; o > 0; o >>= 1) v = fmaxf(v, __shfl_xor_sync(0xffffffffu, v, o));
    int t = threadIdx.x;
    if ((t & 31) == 0) sh[t >> 5] = v;
    __syncthreads();
    if (t < 32) {
        float w = (t < NW) ? sh[t] : -3.4e38f;
#pragma unroll
        for (int o = 16; o > 0; o >>= 1) w = fmaxf(w, __shfl_xor_sync(0xffffffffu, w, o));
        if (t == 0) *bc = w;
    }
    __syncthreads();
    return *bc;
}

// sum qr partials -> relu -> softmax over hw
__global__ void softmax_hw() {
    __shared__ float sh[32];
    __shared__ float bc;
    const int b = blockIdx.x, t = threadIdx.x;
    float v[4];
#pragma unroll
    for (int j = 0; j < 4; j++) {
        const int n = t + j * 1024;
        float s = 0.f;
#pragma unroll
        for (int cb = 0; cb < 8; cb++) s += g_qrp[((size_t)b * 8 + cb) * HW_ + n];
        v[j] = fmaxf(s, 0.f);
    }
    float m = fmaxf(fmaxf(v[0], v[1]), fmaxf(v[2], v[3]));
    const float bm = blockMax<32>(m, sh, &bc);
    float e[4], s = 0.f;
#pragma unroll
    for (int j = 0; j < 4; j++) { e[j] = __expf(v[j] - bm); s += e[j]; }
    const float bs = blockSum<32>(s, sh, &bc);
    const float inv = 1.f / bs;
#pragma unroll
    for (int j = 0; j < 4; j++) g_mask[b * HW_ + t + j * 1024] = e[j] * inv;
}

// fused: reduce part_m -> gx/ctx -> softmax(avg) + layernorm+sigmoid(spatial)
__global__ void fuse_mid() {
    __shared__ float sh[16];
    __shared__ float bc;
    const int b = blockIdx.x, t = threadIdx.x;  // 512 threads
    float s0 = 0.f, s1 = 0.f;
    {
        const int m = t;
        const float* p = g_part_m + (((size_t)b * 8 + (m >> 7)) * 32) * 128 + (m & 127);
#pragma unroll
        for (int nt = 0; nt < 32; nt++) s0 += p[nt * 128];
    }
    {
        const int m = t + 512;
        const float* p = g_part_m + (((size_t)b * 8 + (m >> 7)) * 32) * 128 + (m & 127);
#pragma unroll
        for (int nt = 0; nt < 32; nt++) s1 += p[nt * 128];
    }
    const float v = s0 * (1.f / (float)HW_);
    const float bm = blockMax<16>(v, sh, &bc);
    const float e = __expf(v - bm);
    const float bs = blockSum<16>(e, sh, &bc);
    g_avg[b * CH_ + t] = e / bs;
    const float mean = blockSum<16>(s1, sh, &bc) * (1.f / (float)CH_);
    const float d = s1 - mean;
    const float var = blockSum<16>(d * d, sh, &bc) * (1.f / (float)CH_);
    const float z = d * rsqrtf(var + 1e-5f);
    g_spatial[b * CH_ + t] = 1.f / (1.f + __expf(-z));
}

// ---------------- HMMA GEMM with fused reduction epilogues ----------------
// Block tile M=128, N=128, K=64 per stage. 256 threads (8 warps, 2x4), warp tile 64x32.
// 3-stage cp.async pipeline (16 mainloop iters, 1 barrier each); 2 CTAs/SM.
// Stage: A 128x72 bf16 (18432B) + B 128x72 bf16 (18432B); 3 stages = 110592B.
#define SMEM_GEMM 110592
#define STG_A 18432u
#define RS 72  // smem row stride (elems): 64 + 8 pad; ldsm conflict-free (36 words ≡ 4r mod 32)

template <int PHASE>
__global__ __launch_bounds__(256, 2) void hmma_gemm() {
    extern __shared__ char dsm[];
    const uint32_t sA = s2u(dsm), sB = sA + 3 * STG_A;

    const int tid = threadIdx.x, lid = tid & 31, wid = tid >> 5;
    const int wm = wid & 1, wn = wid >> 1;      // 2 x 4 warp grid: warp tile 64x32
    const int g = lid >> 2, q = lid & 3;
    const int b = blockIdx.z, ntb = blockIdx.x, mtb = blockIdx.y;
    const int n0 = ntb * 128;
    const int m0 = (PHASE == 0 ? 0 : 1024) + mtb * 128;
    const __nv_bfloat16* Wp = g_wbf + (size_t)m0 * 1024;
    const __nv_bfloat16* Xp = g_xbf + ((size_t)b * HW_ + n0) * 1024;

    const int lrow = tid >> 1, lsh = (tid & 1) * 4;  // row 0..127, seg base 0 or 4 (8 segs of 16B)

    float acc[4][4][4];
#pragma unroll
    for (int mt = 0; mt < 4; mt++)
#pragma unroll
        for (int nt = 0; nt < 4; nt++)
#pragma unroll
            for (int e = 0; e < 4; e++) acc[mt][nt][e] = 0.f;

    // ldmatrix lane address components
    const int alane = lid & 15;
    const int ahalf = (lid >> 4) << 3;
    const int brw = (lid & 7) + ((lid >> 4) << 3);
    const int bhalf = ((lid >> 3) & 1) << 3;
    uint32_t aob[4], bob[2];
#pragma unroll
    for (int mt = 0; mt < 4; mt++)
        aob[mt] = (uint32_t)((wm * 64 + mt * 16 + alane) * RS + ahalf) * 2u;
#pragma unroll
    for (int p = 0; p < 2; p++)
        bob[p] = (uint32_t)((wn * 32 + p * 16 + brw) * RS + bhalf) * 2u;

    // stage loader: K=64 slab kb (0..15) into stage sg
#define LOAD_STAGE(kb, sg)                                                                 \
    do {                                                                                   \
        _Pragma("unroll")                                                                  \
        for (int i_ = 0; i_ < 4; i_++) {                                                   \
            const int seg_ = lsh + i_;                                                     \
            cp16(sA + (uint32_t)(sg) * STG_A + (uint32_t)(lrow * RS + seg_ * 8) * 2u,      \
                 Wp + (size_t)lrow * 1024 + (kb) * 64 + seg_ * 8);                         \
            cp16(sB + (uint32_t)(sg) * STG_A + (uint32_t)(lrow * RS + seg_ * 8) * 2u,      \
                 Xp + (size_t)lrow * 1024 + (kb) * 64 + seg_ * 8);                         \
        }                                                                                  \
        CP_COMMIT();                                                                       \
    } while (0)

    LOAD_STAGE(0, 0);
    LOAD_STAGE(1, 1);

    int cs = 0, ls = 2;
    for (int it = 0; it < 16; ++it) {
        if (it < 15) { CP_WAIT(1); } else { CP_WAIT(0); }
        __syncthreads();
        if (it + 2 < 16) LOAD_STAGE(it + 2, ls);

        const uint32_t Ac = sA + (uint32_t)cs * STG_A;
        const uint32_t Bc = sB + (uint32_t)cs * STG_A;
#pragma unroll
        for (int st = 0; st < 4; st++) {
            uint32_t af[4][4], bfr[8];
#pragma unroll
            for (int mt = 0; mt < 4; mt++) ldsm4(af[mt], Ac + aob[mt] + st * 32);
#pragma unroll
            for (int p = 0; p < 2; p++) ldsm4(&bfr[p * 4], Bc + bob[p] + st * 32);
#pragma unroll
            for (int mt = 0; mt < 4; mt++)
#pragma unroll
                for (int nt = 0; nt < 4; nt++) {
                    const int bi = (nt >> 1) * 4 + (nt & 1) * 2;
                    mma16816(acc[mt][nt], af[mt][0], af[mt][1], af[mt][2], af[mt][3],
                             bfr[bi], bfr[bi + 1]);
                }
        }

        cs = (cs == 2) ? 0 : cs + 1;
        ls = (ls == 2) ? 0 : ls + 1;
    }
    __syncthreads();
#undef LOAD_STAGE

    // ---------------- fused reduction epilogue ----------------
    if (PHASE == 0) {
        float* rowred = (float*)dsm;            // [128][4]
        float* mskS = (float*)dsm + 512;        // [128]
        const bool vrm = (mtb >= 4);
        if (vrm && tid < 128) mskS[tid] = g_mask[b * HW_ + n0 + tid];
        __syncthreads();
        float pr[4][2];
#pragma unroll
        for (int mt = 0; mt < 4; mt++) { pr[mt][0] = 0.f; pr[mt][1] = 0.f; }
#pragma unroll
        for (int mt = 0; mt < 4; mt++)
#pragma unroll
            for (int nt = 0; nt < 4; nt++)
#pragma unroll
                for (int rp = 0; rp < 2; rp++)
#pragma unroll
                    for (int e = 0; e < 2; e++) {
                        const float v = fmaxf(acc[mt][nt][rp * 2 + e], 0.f);
                        const int col = wn * 32 + nt * 8 + q * 2 + e;
                        pr[mt][rp] += vrm ? v * mskS[col] : v;
                    }
#pragma unroll
        for (int o = 1; o <= 2; o <<= 1)
#pragma unroll
            for (int mt = 0; mt < 4; mt++)
#pragma unroll
                for (int rp = 0; rp < 2; rp++)
                    pr[mt][rp] += __shfl_xor_sync(0xffffffffu, pr[mt][rp], o);
        if (q == 0) {
#pragma unroll
            for (int mt = 0; mt < 4; mt++)
#pragma unroll
                for (int rp = 0; rp < 2; rp++)
                    rowred[(wm * 64 + mt * 16 + g + rp * 8) * 4 + wn] = pr[mt][rp];
        }
        __syncthreads();
        if (tid < 128) {
            const float s = rowred[tid * 4] + rowred[tid * 4 + 1] +
                            rowred[tid * 4 + 2] + rowred[tid * 4 + 3];
            g_part_m[(((size_t)b * 8 + mtb) * 32 + ntb) * 128 + tid] = s;
        }
    } else {
        float* colred = (float*)dsm;            // [128][2]
        float* avS = (float*)dsm + 256;         // [128]
        if (tid < 128) avS[tid] = g_avg[b * CH_ + mtb * 128 + tid];
        __syncthreads();
        float pc[4][2];
#pragma unroll
        for (int nt = 0; nt < 4; nt++) { pc[nt][0] = 0.f; pc[nt][1] = 0.f; }
#pragma unroll
        for (int mt = 0; mt < 4; mt++)
#pragma unroll
            for (int rp = 0; rp < 2; rp++) {
                const float av = avS[wm * 64 + mt * 16 + g + rp * 8];
#pragma unroll
                for (int nt = 0; nt < 4; nt++)
#pragma unroll
                    for (int e = 0; e < 2; e++)
                        pc[nt][e] += av * fmaxf(acc[mt][nt][rp * 2 + e], 0.f);
            }
#pragma unroll
        for (int o = 4; o <= 16; o <<= 1)
#pragma unroll
            for (int nt = 0; nt < 4; nt++)
#pragma unroll
                for (int e = 0; e < 2; e++)
                    pc[nt][e] += __shfl_xor_sync(0xffffffffu, pc[nt][e], o);
        if (g == 0) {
#pragma unroll
            for (int nt = 0; nt < 4; nt++)
#pragma unroll
                for (int e = 0; e < 2; e++)
                    colred[(wn * 32 + nt * 8 + q * 2 + e) * 2 + wm] = pc[nt][e];
        }
        __syncthreads();
        if (tid < 128) {
            const float s = colred[tid * 2] + colred[tid * 2 + 1];
            g_part_n[(((size_t)b * 32 + ntb) * 4 + mtb) * 128 + tid] = s;
        }
    }
}

// deterministic reduce of part_n + sigmoid
__global__ void reduce_n2() {
    const int i = blockIdx.x * 256 + threadIdx.x;  // 65536
    const int b = i >> 12, n = i & 4095;
    const float* p = g_part_n + (((size_t)b * 32 + (n >> 7)) * 4) * 128 + (n & 127);
    const float s = p[0] + p[128] + p[256] + p[384];
    g_chattn[i] = 1.f / (1.f + __expf(-s));
}

// ---------------- final elementwise combine ----------------
__global__ void combine(const float* __restrict__ x, float* __restrict__ out) {
    const size_t i = (size_t)blockIdx.x * blockDim.x + threadIdx.x;
    const int n4 = (int)(i & 1023);
    const int c  = (int)((i >> 10) & 1023);
    const int b  = (int)(i >> 20);
    const float4 xv = ((const float4*)x)[i];
    const float4 ch = ((const float4*)g_chattn)[(size_t)b * 1024 + n4];
    const float sp = g_spatial[b * CH_ + (c & (CH_ - 1))];
    float4 o;
    if (c < CH_) {
        o.x = fmaf(xv.x, sp * ch.x, xv.x);
        o.y = fmaf(xv.y, sp * ch.y, xv.y);
        o.z = fmaf(xv.z, sp * ch.z, xv.z);
        o.w = fmaf(xv.w, sp * ch.w, xv.w);
    } else {
        o.x = fmaf(xv.x, sp + ch.x, xv.x);
        o.y = fmaf(xv.y, sp + ch.y, xv.y);
        o.z = fmaf(xv.z, sp + ch.z, xv.z);
        o.w = fmaf(xv.w, sp + ch.w, xv.w);
    }
    ((float4*)out)[i] = o;
}

// ---------------- launch ----------------
extern "C" void kernel_launch(void* const* d_in, const int* in_sizes, int n_in,
                              void* d_out, int out_size) {
    const float* x    = (const float*)d_in[0];
    const float* w_qr = (const float*)d_in[1];
    const float* w_vr = (const float*)d_in[2];
    const float* w_ql = (const float*)d_in[3];
    const float* w_vl = (const float*)d_in[4];
    float* out = (float*)d_out;

    cudaFuncSetAttribute(hmma_gemm<0>, cudaFuncAttributeMaxDynamicSharedMemorySize, SMEM_GEMM);
    cudaFuncSetAttribute(hmma_gemm<1>, cudaFuncAttributeMaxDynamicSharedMemorySize, SMEM_GEMM);

    convert_w<<<1536, 512>>>(w_ql, w_vr, w_vl);                        // 1
    transpose_x<<<dim3(HW_ / 32, C_ / 128, B_), 256>>>(x, w_qr);       // 2
    softmax_hw<<<B_, 1024>>>();                                        // 3
    hmma_gemm<0><<<dim3(32, 8, B_), 256, SMEM_GEMM>>>();               // 4  <- ncu target
    fuse_mid<<<B_, 512>>>();                                           // 5
    hmma_gemm<1><<<dim3(32, 4, B_), 256, SMEM_GEMM>>>();               // 6
    reduce_n2<<<256, 256>>>();                                         // 7
    combine<<<(B_ * C_ * HW_ / 4) / 256, 256>>>(x, out);               // 8
}

// round 9
// speedup vs baseline: 1.0454x; 1.0454x over previous
#include <cuda_runtime.h>
#include <cuda_bf16.h>
#include <stdint.h>
#include <math.h>

#define B_  16
#define C_  1024
#define CH_ 512
#define HW_ 4096

// ---------------- device scratch ----------------
__device__ __align__(16) __nv_bfloat16 g_wbf[1536 * 1024];              // stacked [ql;vr;vl] bf16
__device__ __align__(16) __nv_bfloat16 g_xbf[(size_t)B_ * HW_ * 1024];  // xT[b][n][k] bf16
__device__ __align__(16) float g_qrp[B_ * 8 * HW_];  // qr partials per 128-channel block
__device__ __align__(16) float g_mask[B_ * HW_];
__device__ __align__(16) float g_avg[B_ * CH_];
__device__ __align__(16) float g_spatial[B_ * CH_];
__device__ __align__(16) float g_chattn[B_ * HW_];
__device__ __align__(16) float g_part_m[B_ * 8 * 32 * 128];  // (b, mtile8, ntile32, row128)
__device__ __align__(16) float g_part_n[B_ * 32 * 4 * 128];  // (b, ntile32, mtile4, col128)

// ---------------- helpers ----------------
__device__ __forceinline__ uint32_t s2u(const void* p) {
    uint32_t a;
    asm("{ .reg .u64 t; cvta.to.shared.u64 t, %1; cvt.u32.u64 %0, t; }" : "=r"(a) : "l"(p));
    return a;
}
__device__ __forceinline__ void cp16(uint32_t dst, const void* src) {
    asm volatile("cp.async.cg.shared.global [%0], [%1], 16;" :: "r"(dst), "l"(src) : "memory");
}
#define CP_COMMIT() asm volatile("cp.async.commit_group;" ::: "memory")
#define CP_WAIT(n)  asm volatile("cp.async.wait_group %0;" :: "n"(n) : "memory")

__device__ __forceinline__ void ldsm4(uint32_t* r, uint32_t addr) {
    asm volatile("ldmatrix.sync.aligned.m8n8.x4.shared.b16 {%0,%1,%2,%3}, [%4];"
                 : "=r"(r[0]), "=r"(r[1]), "=r"(r[2]), "=r"(r[3]) : "r"(addr));
}

__device__ __forceinline__ void mma16816(float* d, uint32_t a0, uint32_t a1, uint32_t a2,
                                         uint32_t a3, uint32_t b0, uint32_t b1) {
    asm volatile(
        "mma.sync.aligned.m16n8k16.row.col.f32.bf16.bf16.f32 "
        "{%0,%1,%2,%3}, {%4,%5,%6,%7}, {%8,%9}, {%0,%1,%2,%3};"
        : "+f"(d[0]), "+f"(d[1]), "+f"(d[2]), "+f"(d[3])
        : "r"(a0), "r"(a1), "r"(a2), "r"(a3), "r"(b0), "r"(b1));
}

// ---------------- conversion kernels ----------------
__global__ void convert_w(const float* __restrict__ wql, const float* __restrict__ wvr,
                          const float* __restrict__ wvl) {
    const int i = blockIdx.x * 512 + threadIdx.x;  // 786432 pairs
    const int m = i >> 9;
    const int k = (i & 511) * 2;
    const float* src = (m < 512) ? (wql + (size_t)m * 1024)
                                 : ((m < 1024) ? (wvr + (size_t)(m - 512) * 1024)
                                               : (wvl + (size_t)(m - 1024) * 1024));
    __nv_bfloat162 h = __floats2bfloat162_rn(src[k], src[k + 1]);
    ((uint32_t*)g_wbf)[i] = *reinterpret_cast<uint32_t*>(&h);
}

// x[b][c][n] fp32 -> xT[b][n][c] bf16, plus fused partial qr dot product.
__global__ void transpose_x(const float* __restrict__ x, const float* __restrict__ wqr) {
    __shared__ float s[32][129];
    const int tid = threadIdx.x;
    const int n0 = blockIdx.x * 32, c0 = blockIdx.y * 128, b = blockIdx.z;
#pragma unroll
    for (int r = 0; r < 16; r++) {
        const int ci = (tid >> 5) + r * 8;
        const int ni = tid & 31;
        s[ni][ci] = x[((size_t)(b * C_ + c0 + ci)) * HW_ + n0 + ni];
    }
    __syncthreads();
#pragma unroll
    for (int r = 0; r < 8; r++) {
        const int ni = (tid >> 6) + r * 4;
        const int u = tid & 63;
        __nv_bfloat162 h = __floats2bfloat162_rn(s[ni][u * 2], s[ni][u * 2 + 1]);
        ((uint32_t*)g_xbf)[((size_t)(b * HW_ + n0 + ni)) * 512 + (c0 >> 1) + u] =
            *reinterpret_cast<uint32_t*>(&h);
    }
    {
        const int ni = tid >> 3, lg = tid & 7;
        float p = 0.f;
#pragma unroll
        for (int r = 0; r < 16; r++) {
            const int ci = lg * 16 + r;
            p = fmaf(wqr[c0 + ci], s[ni][ci], p);
        }
#pragma unroll
        for (int o = 1; o <= 4; o <<= 1) p += __shfl_xor_sync(0xffffffffu, p, o);
        if (lg == 0) g_qrp[((size_t)b * 8 + blockIdx.y) * HW_ + n0 + ni] = p;
    }
}

// ---------------- small reductions ----------------
template <int NW>
__device__ __forceinline__ float blockSum(float v, float* sh, float* bc) {
#pragma unroll
    for (int o = 16; o > 0; o >>= 1) v += __shfl_xor_sync(0xffffffffu, v, o);
    int t = threadIdx.x;
    if ((t & 31) == 0) sh[t >> 5] = v;
    __syncthreads();
    if (t < 32) {
        float w = (t < NW) ? sh[t] : 0.f;
#pragma unroll
        for (int o = 16; o > 0; o >>= 1) w += __shfl_xor_sync(0xffffffffu, w, o);
        if (t == 0) *bc = w;
    }
    __syncthreads();
    return *bc;
}
template <int NW>
__device__ __forceinline__ float blockMax(float v, float* sh, float* bc) {
#pragma unroll
    for (int o = 16; o > 0; o >>= 1) v = fmaxf(v, __shfl_xor_sync(0xffffffffu, v, o));
    int t = threadIdx.x;
    if ((t & 31) == 0) sh[t >> 5] = v;
    __syncthreads();
    if (t < 32) {
        float w = (t < NW) ? sh[t] : -3.4e38f;
#pragma unroll
        for (int o = 16; o > 0; o >>= 1) w = fmaxf(w, __shfl_xor_sync(0xffffffffu, w, o));
        if (t == 0) *bc = w;
    }
    __syncthreads();
    return *bc;
}

// sum qr partials -> relu -> softmax over hw
__global__ void softmax_hw() {
    __shared__ float sh[32];
    __shared__ float bc;
    const int b = blockIdx.x, t = threadIdx.x;
    float v[4];
#pragma unroll
    for (int j = 0; j < 4; j++) {
        const int n = t + j * 1024;
        float s = 0.f;
#pragma unroll
        for (int cb = 0; cb < 8; cb++) s += g_qrp[((size_t)b * 8 + cb) * HW_ + n];
        v[j] = fmaxf(s, 0.f);
    }
    float m = fmaxf(fmaxf(v[0], v[1]), fmaxf(v[2], v[3]));
    const float bm = blockMax<32>(m, sh, &bc);
    float e[4], s = 0.f;
#pragma unroll
    for (int j = 0; j < 4; j++) { e[j] = __expf(v[j] - bm); s += e[j]; }
    const float bs = blockSum<32>(s, sh, &bc);
    const float inv = 1.f / bs;
#pragma unroll
    for (int j = 0; j < 4; j++) g_mask[b * HW_ + t + j * 1024] = e[j] * inv;
}

// fused: reduce part_m -> gx/ctx -> softmax(avg) + layernorm+sigmoid(spatial)
__global__ void fuse_mid() {
    __shared__ float sh[16];
    __shared__ float bc;
    const int b = blockIdx.x, t = threadIdx.x;  // 512 threads
    float s0 = 0.f, s1 = 0.f;
    {
        const int m = t;
        const float* p = g_part_m + (((size_t)b * 8 + (m >> 7)) * 32) * 128 + (m & 127);
#pragma unroll
        for (int nt = 0; nt < 32; nt++) s0 += p[nt * 128];
    }
    {
        const int m = t + 512;
        const float* p = g_part_m + (((size_t)b * 8 + (m >> 7)) * 32) * 128 + (m & 127);
#pragma unroll
        for (int nt = 0; nt < 32; nt++) s1 += p[nt * 128];
    }
    const float v = s0 * (1.f / (float)HW_);
    const float bm = blockMax<16>(v, sh, &bc);
    const float e = __expf(v - bm);
    const float bs = blockSum<16>(e, sh, &bc);
    g_avg[b * CH_ + t] = e / bs;
    const float mean = blockSum<16>(s1, sh, &bc) * (1.f / (float)CH_);
    const float d = s1 - mean;
    const float var = blockSum<16>(d * d, sh, &bc) * (1.f / (float)CH_);
    const float z = d * rsqrtf(var + 1e-5f);
    g_spatial[b * CH_ + t] = 1.f / (1.f + __expf(-z));
}

// ---------------- HMMA GEMM with fused reduction epilogues ----------------
// Block tile M=128, N=128, K=32. 256 threads (8 warps, 2x4 grid), warp tile 64x32.
// 4-stage cp.async pipeline with relaxed wait discipline (CP_WAIT(2)): stage `it`
// guaranteed landed while it+1, it+2 may still be in flight. 2 CTAs/SM.
// smem: 4 stages x (A 128x40 + B 128x40) bf16 = 4 x 20480B = 81920B.
#define SMEM_GEMM 81920
#define STG 20480u

template <int PHASE>
__global__ __launch_bounds__(256, 2) void hmma_gemm() {
    extern __shared__ char dsm[];
    const uint32_t sA = s2u(dsm);          // A at stage*20480, B at stage*20480 + 10240

    const int tid = threadIdx.x, lid = tid & 31, wid = tid >> 5;
    const int wm = wid & 1, wn = wid >> 1;      // 2 x 4 warp grid: warp tile 64x32
    const int g = lid >> 2, q = lid & 3;
    const int b = blockIdx.z, ntb = blockIdx.x, mtb = blockIdx.y;
    const int n0 = ntb * 128;
    const int m0 = (PHASE == 0 ? 0 : 1024) + mtb * 128;
    const __nv_bfloat16* Wp = g_wbf + (size_t)m0 * 1024;
    const __nv_bfloat16* Xp = g_xbf + ((size_t)b * HW_ + n0) * 1024;

    const int lrow = tid >> 1, lseg0 = (tid & 1) * 2;  // row 0..127, segs {0,1} or {2,3}

    float acc[4][4][4];
#pragma unroll
    for (int mt = 0; mt < 4; mt++)
#pragma unroll
        for (int nt = 0; nt < 4; nt++)
#pragma unroll
            for (int e = 0; e < 4; e++) acc[mt][nt][e] = 0.f;

    // ldmatrix lane address components
    const int alane = lid & 15;
    const int ahalf = (lid >> 4) << 3;
    const int brw = (lid & 7) + ((lid >> 4) << 3);
    const int bhalf = ((lid >> 3) & 1) << 3;
    uint32_t aob[4], bob[2];
#pragma unroll
    for (int mt = 0; mt < 4; mt++)
        aob[mt] = (uint32_t)((wm * 64 + mt * 16 + alane) * 40 + ahalf) * 2u;
#pragma unroll
    for (int p = 0; p < 2; p++)
        bob[p] = (uint32_t)((wn * 32 + p * 16 + brw) * 40 + bhalf) * 2u;

#define LOAD_STAGE(kb, sg)                                                                 \
    do {                                                                                   \
        _Pragma("unroll")                                                                  \
        for (int i_ = 0; i_ < 2; i_++) {                                                   \
            const int seg_ = lseg0 + i_;                                                   \
            cp16(sA + (uint32_t)(sg) * STG + (uint32_t)(lrow * 40 + seg_ * 8) * 2u,        \
                 Wp + (size_t)lrow * 1024 + (kb) * 32 + seg_ * 8);                         \
            cp16(sA + (uint32_t)(sg) * STG + 10240u + (uint32_t)(lrow * 40 + seg_ * 8) * 2u,\
                 Xp + (size_t)lrow * 1024 + (kb) * 32 + seg_ * 8);                         \
        }                                                                                  \
        CP_COMMIT();                                                                       \
    } while (0)

    LOAD_STAGE(0, 0);
    LOAD_STAGE(1, 1);
    LOAD_STAGE(2, 2);

    for (int it = 0; it < 32; ++it) {
        const int cs = it & 3;
        // stage `it` guaranteed complete; it+1/it+2 may remain in flight.
        if (it <= 29) { CP_WAIT(2); }
        else if (it == 30) { CP_WAIT(1); }
        else { CP_WAIT(0); }
        __syncthreads();

        const uint32_t Ac = sA + (uint32_t)cs * STG;
        const uint32_t Bc = Ac + 10240u;

        // substep 0 fragments first (critical path), then issue next prefetch
        uint32_t af[4][4], bfr[8];
#pragma unroll
        for (int mt = 0; mt < 4; mt++) ldsm4(af[mt], Ac + aob[mt]);
#pragma unroll
        for (int p = 0; p < 2; p++) ldsm4(&bfr[p * 4], Bc + bob[p]);

        if (it + 3 < 32) LOAD_STAGE(it + 3, (it + 3) & 3);

#pragma unroll
        for (int mt = 0; mt < 4; mt++)
#pragma unroll
            for (int nt = 0; nt < 4; nt++) {
                const int bi = (nt >> 1) * 4 + (nt & 1) * 2;
                mma16816(acc[mt][nt], af[mt][0], af[mt][1], af[mt][2], af[mt][3],
                         bfr[bi], bfr[bi + 1]);
            }

        // substep 1
#pragma unroll
        for (int mt = 0; mt < 4; mt++) ldsm4(af[mt], Ac + aob[mt] + 32);
#pragma unroll
        for (int p = 0; p < 2; p++) ldsm4(&bfr[p * 4], Bc + bob[p] + 32);
#pragma unroll
        for (int mt = 0; mt < 4; mt++)
#pragma unroll
            for (int nt = 0; nt < 4; nt++) {
                const int bi = (nt >> 1) * 4 + (nt & 1) * 2;
                mma16816(acc[mt][nt], af[mt][0], af[mt][1], af[mt][2], af[mt][3],
                         bfr[bi], bfr[bi + 1]);
            }
        __syncthreads();
    }
#undef LOAD_STAGE

    // ---------------- fused reduction epilogue ----------------
    if (PHASE == 0) {
        float* rowred = (float*)dsm;            // [128][4]
        float* mskS = (float*)dsm + 512;        // [128]
        const bool vrm = (mtb >= 4);
        if (vrm && tid < 128) mskS[tid] = g_mask[b * HW_ + n0 + tid];
        __syncthreads();
        float pr[4][2];
#pragma unroll
        for (int mt = 0; mt < 4; mt++) { pr[mt][0] = 0.f; pr[mt][1] = 0.f; }
#pragma unroll
        for (int mt = 0; mt < 4; mt++)
#pragma unroll
            for (int nt = 0; nt < 4; nt++)
#pragma unroll
                for (int rp = 0; rp < 2; rp++)
#pragma unroll
                    for (int e = 0; e < 2; e++) {
                        const float v = fmaxf(acc[mt][nt][rp * 2 + e], 0.f);
                        const int col = wn * 32 + nt * 8 + q * 2 + e;
                        pr[mt][rp] += vrm ? v * mskS[col] : v;
                    }
#pragma unroll
        for (int o = 1; o <= 2; o <<= 1)
#pragma unroll
            for (int mt = 0; mt < 4; mt++)
#pragma unroll
                for (int rp = 0; rp < 2; rp++)
                    pr[mt][rp] += __shfl_xor_sync(0xffffffffu, pr[mt][rp], o);
        if (q == 0) {
#pragma unroll
            for (int mt = 0; mt < 4; mt++)
#pragma unroll
                for (int rp = 0; rp < 2; rp++)
                    rowred[(wm * 64 + mt * 16 + g + rp * 8) * 4 + wn] = pr[mt][rp];
        }
        __syncthreads();
        if (tid < 128) {
            const float s = rowred[tid * 4] + rowred[tid * 4 + 1] +
                            rowred[tid * 4 + 2] + rowred[tid * 4 + 3];
            g_part_m[(((size_t)b * 8 + mtb) * 32 + ntb) * 128 + tid] = s;
        }
    } else {
        float* colred = (float*)dsm;            // [128][2]
        float* avS = (float*)dsm + 256;         // [128]
        if (tid < 128) avS[tid] = g_avg[b * CH_ + mtb * 128 + tid];
        __syncthreads();
        float pc[4][2];
#pragma unroll
        for (int nt = 0; nt < 4; nt++) { pc[nt][0] = 0.f; pc[nt][1] = 0.f; }
#pragma unroll
        for (int mt = 0; mt < 4; mt++)
#pragma unroll
            for (int rp = 0; rp < 2; rp++) {
                const float av = avS[wm * 64 + mt * 16 + g + rp * 8];
#pragma unroll
                for (int nt = 0; nt < 4; nt++)
#pragma unroll
                    for (int e = 0; e < 2; e++)
                        pc[nt][e] += av * fmaxf(acc[mt][nt][rp * 2 + e], 0.f);
            }
#pragma unroll
        for (int o = 4; o <= 16; o <<= 1)
#pragma unroll
            for (int nt = 0; nt < 4; nt++)
#pragma unroll
                for (int e = 0; e < 2; e++)
                    pc[nt][e] += __shfl_xor_sync(0xffffffffu, pc[nt][e], o);
        if (g == 0) {
#pragma unroll
            for (int nt = 0; nt < 4; nt++)
#pragma unroll
                for (int e = 0; e < 2; e++)
                    colred[(wn * 32 + nt * 8 + q * 2 + e) * 2 + wm] = pc[nt][e];
        }
        __syncthreads();
        if (tid < 128) {
            const float s = colred[tid * 2] + colred[tid * 2 + 1];
            g_part_n[(((size_t)b * 32 + ntb) * 4 + mtb) * 128 + tid] = s;
        }
    }
}

// deterministic reduce of part_n + sigmoid
__global__ void reduce_n2() {
    const int i = blockIdx.x * 256 + threadIdx.x;  // 65536
    const int b = i >> 12, n = i & 4095;
    const float* p = g_part_n + (((size_t)b * 32 + (n >> 7)) * 4) * 128 + (n & 127);
    const float s = p[0] + p[128] + p[256] + p[384];
    g_chattn[i] = 1.f / (1.f + __expf(-s));
}

// ---------------- final elementwise combine ----------------
__global__ void combine(const float* __restrict__ x, float* __restrict__ out) {
    const size_t i = (size_t)blockIdx.x * blockDim.x + threadIdx.x;
    const int n4 = (int)(i & 1023);
    const int c  = (int)((i >> 10) & 1023);
    const int b  = (int)(i >> 20);
    const float4 xv = ((const float4*)x)[i];
    const float4 ch = ((const float4*)g_chattn)[(size_t)b * 1024 + n4];
    const float sp = g_spatial[b * CH_ + (c & (CH_ - 1))];
    float4 o;
    if (c < CH_) {
        o.x = fmaf(xv.x, sp * ch.x, xv.x);
        o.y = fmaf(xv.y, sp * ch.y, xv.y);
        o.z = fmaf(xv.z, sp * ch.z, xv.z);
        o.w = fmaf(xv.w, sp * ch.w, xv.w);
    } else {
        o.x = fmaf(xv.x, sp + ch.x, xv.x);
        o.y = fmaf(xv.y, sp + ch.y, xv.y);
        o.z = fmaf(xv.z, sp + ch.z, xv.z);
        o.w = fmaf(xv.w, sp + ch.w, xv.w);
    }
    ((float4*)out)[i] = o;
}

// ---------------- launch ----------------
extern "C" void kernel_launch(void* const* d_in, const int* in_sizes, int n_in,
                              void* d_out, int out_size) {
    const float* x    = (const float*)d_in[0];
    const float* w_qr = (const float*)d_in[1];
    const float* w_vr = (const float*)d_in[2];
    const float* w_ql = (const float*)d_in[3];
    const float* w_vl = (const float*)d_in[4];
    float* out = (float*)d_out;

    cudaFuncSetAttribute(hmma_gemm<0>, cudaFuncAttributeMaxDynamicSharedMemorySize, SMEM_GEMM);
    cudaFuncSetAttribute(hmma_gemm<1>, cudaFuncAttributeMaxDynamicSharedMemorySize, SMEM_GEMM);

    convert_w<<<1536, 512>>>(w_ql, w_vr, w_vl);                        // 1
    transpose_x<<<dim3(HW_ / 32, C_ / 128, B_), 256>>>(x, w_qr);       // 2
    softmax_hw<<<B_, 1024>>>();                                        // 3
    hmma_gemm<0><<<dim3(32, 8, B_), 256, SMEM_GEMM>>>();               // 4  <- ncu target
    fuse_mid<<<B_, 512>>>();                                           // 5
    hmma_gemm<1><<<dim3(32, 4, B_), 256, SMEM_GEMM>>>();               // 6
    reduce_n2<<<256, 256>>>();                                         // 7
    combine<<<(B_ * C_ * HW_ / 4) / 256, 256>>>(x, out);               // 8
}

// round 10
// speedup vs baseline: 1.1047x; 1.0567x over previous
#include <cuda_runtime.h>
#include <cuda_bf16.h>
#include <stdint.h>
#include <math.h>

#define B_  16
#define C_  1024
#define CH_ 512
#define HW_ 4096

// ---------------- device scratch ----------------
__device__ __align__(16) __nv_bfloat16 g_wbf[1536 * 1024];              // stacked [ql;vr;vl] bf16
__device__ __align__(16) __nv_bfloat16 g_xbf[(size_t)B_ * HW_ * 1024];  // xT[b][n][k] bf16
__device__ __align__(16) float g_qrp[B_ * 8 * HW_];  // qr partials per 128-channel block
__device__ __align__(16) float g_mask[B_ * HW_];
__device__ __align__(16) float g_avg[B_ * CH_];
__device__ __align__(16) float g_spatial[B_ * CH_];
__device__ __align__(16) float g_chattn[B_ * HW_];
__device__ __align__(16) float g_part_m[B_ * 8 * 32 * 128];  // (b, mtile8, ntile32, row128)
__device__ __align__(16) float g_part_n[B_ * 32 * 4 * 128];  // (b, ntile32, mtile4, col128)

// ---------------- helpers ----------------
__device__ __forceinline__ uint32_t s2u(const void* p) {
    uint32_t a;
    asm("{ .reg .u64 t; cvta.to.shared.u64 t, %1; cvt.u32.u64 %0, t; }" : "=r"(a) : "l"(p));
    return a;
}
__device__ __forceinline__ void cp16(uint32_t dst, const void* src) {
    asm volatile("cp.async.cg.shared.global [%0], [%1], 16;" :: "r"(dst), "l"(src) : "memory");
}
#define CP_COMMIT() asm volatile("cp.async.commit_group;" ::: "memory")
#define CP_WAIT(n)  asm volatile("cp.async.wait_group %0;" :: "n"(n) : "memory")

__device__ __forceinline__ void ldsm4(uint32_t* r, uint32_t addr) {
    asm volatile("ldmatrix.sync.aligned.m8n8.x4.shared.b16 {%0,%1,%2,%3}, [%4];"
                 : "=r"(r[0]), "=r"(r[1]), "=r"(r[2]), "=r"(r[3]) : "r"(addr));
}

__device__ __forceinline__ void mma16816(float* d, uint32_t a0, uint32_t a1, uint32_t a2,
                                         uint32_t a3, uint32_t b0, uint32_t b1) {
    asm volatile(
        "mma.sync.aligned.m16n8k16.row.col.f32.bf16.bf16.f32 "
        "{%0,%1,%2,%3}, {%4,%5,%6,%7}, {%8,%9}, {%0,%1,%2,%3};"
        : "+f"(d[0]), "+f"(d[1]), "+f"(d[2]), "+f"(d[3])
        : "r"(a0), "r"(a1), "r"(a2), "r"(a3), "r"(b0), "r"(b1));
}

// ---------------- conversion kernels ----------------
__global__ void convert_w(const float* __restrict__ wql, const float* __restrict__ wvr,
                          const float* __restrict__ wvl) {
    const int i = blockIdx.x * 512 + threadIdx.x;  // 786432 pairs
    const int m = i >> 9;
    const int k = (i & 511) * 2;
    const float* src = (m < 512) ? (wql + (size_t)m * 1024)
                                 : ((m < 1024) ? (wvr + (size_t)(m - 512) * 1024)
                                               : (wvl + (size_t)(m - 1024) * 1024));
    __nv_bfloat162 h = __floats2bfloat162_rn(src[k], src[k + 1]);
    ((uint32_t*)g_wbf)[i] = *reinterpret_cast<uint32_t*>(&h);
}

// x[b][c][n] fp32 -> xT[b][n][c] bf16, plus fused partial qr dot product.
__global__ void transpose_x(const float* __restrict__ x, const float* __restrict__ wqr) {
    __shared__ float s[32][129];
    const int tid = threadIdx.x;
    const int n0 = blockIdx.x * 32, c0 = blockIdx.y * 128, b = blockIdx.z;
#pragma unroll
    for (int r = 0; r < 16; r++) {
        const int ci = (tid >> 5) + r * 8;
        const int ni = tid & 31;
        s[ni][ci] = x[((size_t)(b * C_ + c0 + ci)) * HW_ + n0 + ni];
    }
    __syncthreads();
#pragma unroll
    for (int r = 0; r < 8; r++) {
        const int ni = (tid >> 6) + r * 4;
        const int u = tid & 63;
        __nv_bfloat162 h = __floats2bfloat162_rn(s[ni][u * 2], s[ni][u * 2 + 1]);
        ((uint32_t*)g_xbf)[((size_t)(b * HW_ + n0 + ni)) * 512 + (c0 >> 1) + u] =
            *reinterpret_cast<uint32_t*>(&h);
    }
    {
        const int ni = tid >> 3, lg = tid & 7;
        float p = 0.f;
#pragma unroll
        for (int r = 0; r < 16; r++) {
            const int ci = lg * 16 + r;
            p = fmaf(wqr[c0 + ci], s[ni][ci], p);
        }
#pragma unroll
        for (int o = 1; o <= 4; o <<= 1) p += __shfl_xor_sync(0xffffffffu, p, o);
        if (lg == 0) g_qrp[((size_t)b * 8 + blockIdx.y) * HW_ + n0 + ni] = p;
    }
}

// ---------------- small reductions ----------------
template <int NW>
__device__ __forceinline__ float blockSum(float v, float* sh, float* bc) {
#pragma unroll
    for (int o = 16; o > 0; o >>= 1) v += __shfl_xor_sync(0xffffffffu, v, o);
    int t = threadIdx.x;
    if ((t & 31) == 0) sh[t >> 5] = v;
    __syncthreads();
    if (t < 32) {
        float w = (t < NW) ? sh[t] : 0.f;
#pragma unroll
        for (int o = 16; o > 0; o >>= 1) w += __shfl_xor_sync(0xffffffffu, w, o);
        if (t == 0) *bc = w;
    }
    __syncthreads();
    return *bc;
}
template <int NW>
__device__ __forceinline__ float blockMax(float v, float* sh, float* bc) {
#pragma unroll
    for (int o = 16; o > 0; o >>= 1) v = fmaxf(v, __shfl_xor_sync(0xffffffffu, v, o));
    int t = threadIdx.x;
    if ((t & 31) == 0) sh[t >> 5] = v;
    __syncthreads();
    if (t < 32) {
        float w = (t < NW) ? sh[t] : -3.4e38f;
#pragma unroll
        for (int o = 16; o > 0; o >>= 1) w = fmaxf(w, __shfl_xor_sync(0xffffffffu, w, o));
        if (t == 0) *bc = w;
    }
    __syncthreads();
    return *bc;
}

// sum qr partials -> relu -> softmax over hw
__global__ void softmax_hw() {
    __shared__ float sh[32];
    __shared__ float bc;
    const int b = blockIdx.x, t = threadIdx.x;
    float v[4];
#pragma unroll
    for (int j = 0; j < 4; j++) {
        const int n = t + j * 1024;
        float s = 0.f;
#pragma unroll
        for (int cb = 0; cb < 8; cb++) s += g_qrp[((size_t)b * 8 + cb) * HW_ + n];
        v[j] = fmaxf(s, 0.f);
    }
    float m = fmaxf(fmaxf(v[0], v[1]), fmaxf(v[2], v[3]));
    const float bm = blockMax<32>(m, sh, &bc);
    float e[4], s = 0.f;
#pragma unroll
    for (int j = 0; j < 4; j++) { e[j] = __expf(v[j] - bm); s += e[j]; }
    const float bs = blockSum<32>(s, sh, &bc);
    const float inv = 1.f / bs;
#pragma unroll
    for (int j = 0; j < 4; j++) g_mask[b * HW_ + t + j * 1024] = e[j] * inv;
}

// fused: reduce part_m -> gx/ctx -> softmax(avg) + layernorm+sigmoid(spatial)
__global__ void fuse_mid() {
    __shared__ float sh[16];
    __shared__ float bc;
    const int b = blockIdx.x, t = threadIdx.x;  // 512 threads
    float s0 = 0.f, s1 = 0.f;
    {
        const int m = t;
        const float* p = g_part_m + (((size_t)b * 8 + (m >> 7)) * 32) * 128 + (m & 127);
#pragma unroll
        for (int nt = 0; nt < 32; nt++) s0 += p[nt * 128];
    }
    {
        const int m = t + 512;
        const float* p = g_part_m + (((size_t)b * 8 + (m >> 7)) * 32) * 128 + (m & 127);
#pragma unroll
        for (int nt = 0; nt < 32; nt++) s1 += p[nt * 128];
    }
    const float v = s0 * (1.f / (float)HW_);
    const float bm = blockMax<16>(v, sh, &bc);
    const float e = __expf(v - bm);
    const float bs = blockSum<16>(e, sh, &bc);
    g_avg[b * CH_ + t] = e / bs;
    const float mean = blockSum<16>(s1, sh, &bc) * (1.f / (float)CH_);
    const float d = s1 - mean;
    const float var = blockSum<16>(d * d, sh, &bc) * (1.f / (float)CH_);
    const float z = d * rsqrtf(var + 1e-5f);
    g_spatial[b * CH_ + t] = 1.f / (1.f + __expf(-z));
}

// ---------------- HMMA GEMM with fused reduction epilogues ----------------
// Round-7 config: block tile M=128, N=128, K=32; 256 threads (8 warps, 2x4),
// warp tile 64x32; 3-stage cp.async pipeline; 2 CTAs/SM.
// NEW: warp-phase stagger — odd warps run the two k16 substeps in order (1,0),
// so at any instant ~half the warps use the smem crossbar (LDSM) while the
// other half use the tensor pipe (HMMA), breaking the phase convoy.
#define SMEM_GEMM 61440
#define STG 20480u

template <int PHASE>
__global__ __launch_bounds__(256, 2) void hmma_gemm() {
    extern __shared__ char dsm[];
    const uint32_t sA = s2u(dsm);          // A at stage*20480, B at stage*20480 + 10240

    const int tid = threadIdx.x, lid = tid & 31, wid = tid >> 5;
    const int wm = wid & 1, wn = wid >> 1;      // 2 x 4 warp grid: warp tile 64x32
    const int g = lid >> 2, q = lid & 3;
    const int stsel = wid & 1;                  // substep-order stagger
    const int b = blockIdx.z, ntb = blockIdx.x, mtb = blockIdx.y;
    const int n0 = ntb * 128;
    const int m0 = (PHASE == 0 ? 0 : 1024) + mtb * 128;
    const __nv_bfloat16* Wp = g_wbf + (size_t)m0 * 1024;
    const __nv_bfloat16* Xp = g_xbf + ((size_t)b * HW_ + n0) * 1024;

    const int lrow = tid >> 1, lseg0 = (tid & 1) * 2;  // row 0..127, segs {0,1} or {2,3}

    float acc[4][4][4];
#pragma unroll
    for (int mt = 0; mt < 4; mt++)
#pragma unroll
        for (int nt = 0; nt < 4; nt++)
#pragma unroll
            for (int e = 0; e < 4; e++) acc[mt][nt][e] = 0.f;

    // ldmatrix lane address components
    const int alane = lid & 15;
    const int ahalf = (lid >> 4) << 3;
    const int brw = (lid & 7) + ((lid >> 4) << 3);
    const int bhalf = ((lid >> 3) & 1) << 3;
    uint32_t aob[4], bob[2];
#pragma unroll
    for (int mt = 0; mt < 4; mt++)
        aob[mt] = (uint32_t)((wm * 64 + mt * 16 + alane) * 40 + ahalf) * 2u;
#pragma unroll
    for (int p = 0; p < 2; p++)
        bob[p] = (uint32_t)((wn * 32 + p * 16 + brw) * 40 + bhalf) * 2u;

#define LOAD_STAGE(kb, sg)                                                                  \
    do {                                                                                    \
        _Pragma("unroll")                                                                   \
        for (int i_ = 0; i_ < 2; i_++) {                                                    \
            const int seg_ = lseg0 + i_;                                                    \
            cp16(sA + (uint32_t)(sg) * STG + (uint32_t)(lrow * 40 + seg_ * 8) * 2u,         \
                 Wp + (size_t)lrow * 1024 + (kb) * 32 + seg_ * 8);                          \
            cp16(sA + (uint32_t)(sg) * STG + 10240u + (uint32_t)(lrow * 40 + seg_ * 8) * 2u,\
                 Xp + (size_t)lrow * 1024 + (kb) * 32 + seg_ * 8);                          \
        }                                                                                   \
        CP_COMMIT();                                                                        \
    } while (0)

    LOAD_STAGE(0, 0);
    LOAD_STAGE(1, 1);

    int cs = 0, ls = 2;
    for (int it = 0; it < 32; ++it) {
        if (it < 31) { CP_WAIT(1); } else { CP_WAIT(0); }
        __syncthreads();
        if (it + 2 < 32) LOAD_STAGE(it + 2, ls);

        const uint32_t Ac = sA + (uint32_t)cs * STG;
        const uint32_t Bc = Ac + 10240u;
#pragma unroll
        for (int s = 0; s < 2; s++) {
            const int st = s ^ stsel;           // odd warps: substep order 1,0
            uint32_t af[4][4], bfr[8];
#pragma unroll
            for (int mt = 0; mt < 4; mt++) ldsm4(af[mt], Ac + aob[mt] + st * 32);
#pragma unroll
            for (int p = 0; p < 2; p++) ldsm4(&bfr[p * 4], Bc + bob[p] + st * 32);
#pragma unroll
            for (int mt = 0; mt < 4; mt++)
#pragma unroll
                for (int nt = 0; nt < 4; nt++) {
                    const int bi = (nt >> 1) * 4 + (nt & 1) * 2;
                    mma16816(acc[mt][nt], af[mt][0], af[mt][1], af[mt][2], af[mt][3],
                             bfr[bi], bfr[bi + 1]);
                }
        }

        cs = (cs == 2) ? 0 : cs + 1;
        ls = (ls == 2) ? 0 : ls + 1;
    }
    __syncthreads();
#undef LOAD_STAGE

    // ---------------- fused reduction epilogue ----------------
    if (PHASE == 0) {
        float* rowred = (float*)dsm;            // [128][4]
        float* mskS = (float*)dsm + 512;        // [128]
        const bool vrm = (mtb >= 4);
        if (vrm && tid < 128) mskS[tid] = g_mask[b * HW_ + n0 + tid];
        __syncthreads();
        float pr[4][2];
#pragma unroll
        for (int mt = 0; mt < 4; mt++) { pr[mt][0] = 0.f; pr[mt][1] = 0.f; }
#pragma unroll
        for (int mt = 0; mt < 4; mt++)
#pragma unroll
            for (int nt = 0; nt < 4; nt++)
#pragma unroll
                for (int rp = 0; rp < 2; rp++)
#pragma unroll
                    for (int e = 0; e < 2; e++) {
                        const float v = fmaxf(acc[mt][nt][rp * 2 + e], 0.f);
                        const int col = wn * 32 + nt * 8 + q * 2 + e;
                        pr[mt][rp] += vrm ? v * mskS[col] : v;
                    }
#pragma unroll
        for (int o = 1; o <= 2; o <<= 1)
#pragma unroll
            for (int mt = 0; mt < 4; mt++)
#pragma unroll
                for (int rp = 0; rp < 2; rp++)
                    pr[mt][rp] += __shfl_xor_sync(0xffffffffu, pr[mt][rp], o);
        if (q == 0) {
#pragma unroll
            for (int mt = 0; mt < 4; mt++)
#pragma unroll
                for (int rp = 0; rp < 2; rp++)
                    rowred[(wm * 64 + mt * 16 + g + rp * 8) * 4 + wn] = pr[mt][rp];
        }
        __syncthreads();
        if (tid < 128) {
            const float s = rowred[tid * 4] + rowred[tid * 4 + 1] +
                            rowred[tid * 4 + 2] + rowred[tid * 4 + 3];
            g_part_m[(((size_t)b * 8 + mtb) * 32 + ntb) * 128 + tid] = s;
        }
    } else {
        float* colred = (float*)dsm;            // [128][2]
        float* avS = (float*)dsm + 256;         // [128]
        if (tid < 128) avS[tid] = g_avg[b * CH_ + mtb * 128 + tid];
        __syncthreads();
        float pc[4][2];
#pragma unroll
        for (int nt = 0; nt < 4; nt++) { pc[nt][0] = 0.f; pc[nt][1] = 0.f; }
#pragma unroll
        for (int mt = 0; mt < 4; mt++)
#pragma unroll
            for (int rp = 0; rp < 2; rp++) {
                const float av = avS[wm * 64 + mt * 16 + g + rp * 8];
#pragma unroll
                for (int nt = 0; nt < 4; nt++)
#pragma unroll
                    for (int e = 0; e < 2; e++)
                        pc[nt][e] += av * fmaxf(acc[mt][nt][rp * 2 + e], 0.f);
            }
#pragma unroll
        for (int o = 4; o <= 16; o <<= 1)
#pragma unroll
            for (int nt = 0; nt < 4; nt++)
#pragma unroll
                for (int e = 0; e < 2; e++)
                    pc[nt][e] += __shfl_xor_sync(0xffffffffu, pc[nt][e], o);
        if (g == 0) {
#pragma unroll
            for (int nt = 0; nt < 4; nt++)
#pragma unroll
                for (int e = 0; e < 2; e++)
                    colred[(wn * 32 + nt * 8 + q * 2 + e) * 2 + wm] = pc[nt][e];
        }
        __syncthreads();
        if (tid < 128) {
            const float s = colred[tid * 2] + colred[tid * 2 + 1];
            g_part_n[(((size_t)b * 32 + ntb) * 4 + mtb) * 128 + tid] = s;
        }
    }
}

// deterministic reduce of part_n + sigmoid
__global__ void reduce_n2() {
    const int i = blockIdx.x * 256 + threadIdx.x;  // 65536
    const int b = i >> 12, n = i & 4095;
    const float* p = g_part_n + (((size_t)b * 32 + (n >> 7)) * 4) * 128 + (n & 127);
    const float s = p[0] + p[128] + p[256] + p[384];
    g_chattn[i] = 1.f / (1.f + __expf(-s));
}

// ---------------- final elementwise combine ----------------
__global__ void combine(const float* __restrict__ x, float* __restrict__ out) {
    const size_t i = (size_t)blockIdx.x * blockDim.x + threadIdx.x;
    const int n4 = (int)(i & 1023);
    const int c  = (int)((i >> 10) & 1023);
    const int b  = (int)(i >> 20);
    const float4 xv = ((const float4*)x)[i];
    const float4 ch = ((const float4*)g_chattn)[(size_t)b * 1024 + n4];
    const float sp = g_spatial[b * CH_ + (c & (CH_ - 1))];
    float4 o;
    if (c < CH_) {
        o.x = fmaf(xv.x, sp * ch.x, xv.x);
        o.y = fmaf(xv.y, sp * ch.y, xv.y);
        o.z = fmaf(xv.z, sp * ch.z, xv.z);
        o.w = fmaf(xv.w, sp * ch.w, xv.w);
    } else {
        o.x = fmaf(xv.x, sp + ch.x, xv.x);
        o.y = fmaf(xv.y, sp + ch.y, xv.y);
        o.z = fmaf(xv.z, sp + ch.z, xv.z);
        o.w = fmaf(xv.w, sp + ch.w, xv.w);
    }
    ((float4*)out)[i] = o;
}

// ---------------- launch ----------------
extern "C" void kernel_launch(void* const* d_in, const int* in_sizes, int n_in,
                              void* d_out, int out_size) {
    const float* x    = (const float*)d_in[0];
    const float* w_qr = (const float*)d_in[1];
    const float* w_vr = (const float*)d_in[2];
    const float* w_ql = (const float*)d_in[3];
    const float* w_vl = (const float*)d_in[4];
    float* out = (float*)d_out;

    cudaFuncSetAttribute(hmma_gemm<0>, cudaFuncAttributeMaxDynamicSharedMemorySize, SMEM_GEMM);
    cudaFuncSetAttribute(hmma_gemm<1>, cudaFuncAttributeMaxDynamicSharedMemorySize, SMEM_GEMM);

    convert_w<<<1536, 512>>>(w_ql, w_vr, w_vl);                        // 1
    transpose_x<<<dim3(HW_ / 32, C_ / 128, B_), 256>>>(x, w_qr);       // 2
    softmax_hw<<<B_, 1024>>>();                                        // 3
    hmma_gemm<0><<<dim3(32, 8, B_), 256, SMEM_GEMM>>>();               // 4  <- ncu target
    fuse_mid<<<B_, 512>>>();                                           // 5
    hmma_gemm<1><<<dim3(32, 4, B_), 256, SMEM_GEMM>>>();               // 6
    reduce_n2<<<256, 256>>>();                                         // 7
    combine<<<(B_ * C_ * HW_ / 4) / 256, 256>>>(x, out);               // 8
}

// round 11
// speedup vs baseline: 1.2008x; 1.0870x over previous
#include <cuda_runtime.h>
#include <cuda_bf16.h>
#include <stdint.h>
#include <math.h>

#define B_  16
#define C_  1024
#define CH_ 512
#define HW_ 4096

// ---------------- device scratch ----------------
__device__ __align__(16) __nv_bfloat16 g_wbf[1536 * 1024];              // stacked [ql;vr;vl] bf16
__device__ __align__(16) __nv_bfloat16 g_xbf[(size_t)B_ * HW_ * 1024];  // xT[b][n][k] bf16
__device__ __align__(16) float g_qrp[B_ * 8 * HW_];  // qr partials per 128-channel block
__device__ __align__(16) float g_mask[B_ * HW_];
__device__ __align__(16) float g_avg[B_ * CH_];
__device__ __align__(16) float g_spatial[B_ * CH_];
__device__ __align__(16) float g_chattn[B_ * HW_];
__device__ __align__(16) float g_part_m[B_ * 8 * 32 * 128];  // (b, mtile8, ntile32, row128)
__device__ __align__(16) float g_part_n[B_ * 32 * 4 * 128];  // (b, ntile32, mtile4, col128)

// ---------------- helpers ----------------
__device__ __forceinline__ uint32_t s2u(const void* p) {
    uint32_t a;
    asm("{ .reg .u64 t; cvta.to.shared.u64 t, %1; cvt.u32.u64 %0, t; }" : "=r"(a) : "l"(p));
    return a;
}
__device__ __forceinline__ void cp16(uint32_t dst, const void* src) {
    asm volatile("cp.async.cg.shared.global [%0], [%1], 16;" :: "r"(dst), "l"(src) : "memory");
}
#define CP_COMMIT() asm volatile("cp.async.commit_group;" ::: "memory")
#define CP_WAIT(n)  asm volatile("cp.async.wait_group %0;" :: "n"(n) : "memory")

__device__ __forceinline__ void ldsm4(uint32_t* r, uint32_t addr) {
    asm volatile("ldmatrix.sync.aligned.m8n8.x4.shared.b16 {%0,%1,%2,%3}, [%4];"
                 : "=r"(r[0]), "=r"(r[1]), "=r"(r[2]), "=r"(r[3]) : "r"(addr));
}

__device__ __forceinline__ void mma16816(float* d, uint32_t a0, uint32_t a1, uint32_t a2,
                                         uint32_t a3, uint32_t b0, uint32_t b1) {
    asm volatile(
        "mma.sync.aligned.m16n8k16.row.col.f32.bf16.bf16.f32 "
        "{%0,%1,%2,%3}, {%4,%5,%6,%7}, {%8,%9}, {%0,%1,%2,%3};"
        : "+f"(d[0]), "+f"(d[1]), "+f"(d[2]), "+f"(d[3])
        : "r"(a0), "r"(a1), "r"(a2), "r"(a3), "r"(b0), "r"(b1));
}

// ---------------- conversion kernels ----------------
__global__ void convert_w(const float* __restrict__ wql, const float* __restrict__ wvr,
                          const float* __restrict__ wvl) {
    const int i = blockIdx.x * 512 + threadIdx.x;  // 786432 pairs
    const int m = i >> 9;
    const int k = (i & 511) * 2;
    const float* src = (m < 512) ? (wql + (size_t)m * 1024)
                                 : ((m < 1024) ? (wvr + (size_t)(m - 512) * 1024)
                                               : (wvl + (size_t)(m - 1024) * 1024));
    __nv_bfloat162 h = __floats2bfloat162_rn(src[k], src[k + 1]);
    ((uint32_t*)g_wbf)[i] = *reinterpret_cast<uint32_t*>(&h);
}

// x[b][c][n] fp32 -> xT[b][n][c] bf16, plus fused partial qr dot product.
__global__ void transpose_x(const float* __restrict__ x, const float* __restrict__ wqr) {
    __shared__ float s[32][129];
    const int tid = threadIdx.x;
    const int n0 = blockIdx.x * 32, c0 = blockIdx.y * 128, b = blockIdx.z;
#pragma unroll
    for (int r = 0; r < 16; r++) {
        const int ci = (tid >> 5) + r * 8;
        const int ni = tid & 31;
        s[ni][ci] = x[((size_t)(b * C_ + c0 + ci)) * HW_ + n0 + ni];
    }
    __syncthreads();
#pragma unroll
    for (int r = 0; r < 8; r++) {
        const int ni = (tid >> 6) + r * 4;
        const int u = tid & 63;
        __nv_bfloat162 h = __floats2bfloat162_rn(s[ni][u * 2], s[ni][u * 2 + 1]);
        ((uint32_t*)g_xbf)[((size_t)(b * HW_ + n0 + ni)) * 512 + (c0 >> 1) + u] =
            *reinterpret_cast<uint32_t*>(&h);
    }
    {
        const int ni = tid >> 3, lg = tid & 7;
        float p = 0.f;
#pragma unroll
        for (int r = 0; r < 16; r++) {
            const int ci = lg * 16 + r;
            p = fmaf(wqr[c0 + ci], s[ni][ci], p);
        }
#pragma unroll
        for (int o = 1; o <= 4; o <<= 1) p += __shfl_xor_sync(0xffffffffu, p, o);
        if (lg == 0) g_qrp[((size_t)b * 8 + blockIdx.y) * HW_ + n0 + ni] = p;
    }
}

// ---------------- small reductions ----------------
template <int NW>
__device__ __forceinline__ float blockSum(float v, float* sh, float* bc) {
#pragma unroll
    for (int o = 16; o > 0; o >>= 1) v += __shfl_xor_sync(0xffffffffu, v, o);
    int t = threadIdx.x;
    if ((t & 31) == 0) sh[t >> 5] = v;
    __syncthreads();
    if (t < 32) {
        float w = (t < NW) ? sh[t] : 0.f;
#pragma unroll
        for (int o = 16; o > 0; o >>= 1) w += __shfl_xor_sync(0xffffffffu, w, o);
        if (t == 0) *bc = w;
    }
    __syncthreads();
    return *bc;
}
template <int NW>
__device__ __forceinline__ float blockMax(float v, float* sh, float* bc) {
#pragma unroll
    for (int o = 16; o > 0; o >>= 1) v = fmaxf(v, __shfl_xor_sync(0xffffffffu, v, o));
    int t = threadIdx.x;
    if ((t & 31) == 0) sh[t >> 5] = v;
    __syncthreads();
    if (t < 32) {
        float w = (t < NW) ? sh[t] : -3.4e38f;
#pragma unroll
        for (int o = 16; o > 0; o >>= 1) w = fmaxf(w, __shfl_xor_sync(0xffffffffu, w, o));
        if (t == 0) *bc = w;
    }
    __syncthreads();
    return *bc;
}

// sum qr partials -> relu -> softmax over hw
__global__ void softmax_hw() {
    __shared__ float sh[32];
    __shared__ float bc;
    const int b = blockIdx.x, t = threadIdx.x;
    float v[4];
#pragma unroll
    for (int j = 0; j < 4; j++) {
        const int n = t + j * 1024;
        float s = 0.f;
#pragma unroll
        for (int cb = 0; cb < 8; cb++) s += g_qrp[((size_t)b * 8 + cb) * HW_ + n];
        v[j] = fmaxf(s, 0.f);
    }
    float m = fmaxf(fmaxf(v[0], v[1]), fmaxf(v[2], v[3]));
    const float bm = blockMax<32>(m, sh, &bc);
    float e[4], s = 0.f;
#pragma unroll
    for (int j = 0; j < 4; j++) { e[j] = __expf(v[j] - bm); s += e[j]; }
    const float bs = blockSum<32>(s, sh, &bc);
    const float inv = 1.f / bs;
#pragma unroll
    for (int j = 0; j < 4; j++) g_mask[b * HW_ + t + j * 1024] = e[j] * inv;
}

// fused: reduce part_m -> gx/ctx -> softmax(avg) + layernorm+sigmoid(spatial)
__global__ void fuse_mid() {
    __shared__ float sh[16];
    __shared__ float bc;
    const int b = blockIdx.x, t = threadIdx.x;  // 512 threads
    float s0 = 0.f, s1 = 0.f;
    {
        const int m = t;
        const float* p = g_part_m + (((size_t)b * 8 + (m >> 7)) * 32) * 128 + (m & 127);
#pragma unroll
        for (int nt = 0; nt < 32; nt++) s0 += p[nt * 128];
    }
    {
        const int m = t + 512;
        const float* p = g_part_m + (((size_t)b * 8 + (m >> 7)) * 32) * 128 + (m & 127);
#pragma unroll
        for (int nt = 0; nt < 32; nt++) s1 += p[nt * 128];
    }
    const float v = s0 * (1.f / (float)HW_);
    const float bm = blockMax<16>(v, sh, &bc);
    const float e = __expf(v - bm);
    const float bs = blockSum<16>(e, sh, &bc);
    g_avg[b * CH_ + t] = e / bs;
    const float mean = blockSum<16>(s1, sh, &bc) * (1.f / (float)CH_);
    const float d = s1 - mean;
    const float var = blockSum<16>(d * d, sh, &bc) * (1.f / (float)CH_);
    const float z = d * rsqrtf(var + 1e-5f);
    g_spatial[b * CH_ + t] = 1.f / (1.f + __expf(-z));
}

// ---------------- HMMA GEMM with fused reduction epilogues ----------------
// Block tile M=128, N=128, K=32; 256 threads (8 warps, 2x4), warp tile 64x32.
// 5-stage cp.async pipeline, __syncthreads only every 2 iterations -> warps may
// drift a full iteration, overlapping one warp's LDSM burst with another's HMMA
// burst (de-convoy). Stage reuse gaps are 2..4 mod 5 -> safe under drift.
// 2 CTAs/SM (smem 102400B/CTA, regs <=128).
#define SMEM_GEMM 102400
#define STG 20480u

template <int PHASE>
__global__ __launch_bounds__(256, 2) void hmma_gemm() {
    extern __shared__ char dsm[];
    const uint32_t sA = s2u(dsm);          // A at stage*20480, B at stage*20480 + 10240

    const int tid = threadIdx.x, lid = tid & 31, wid = tid >> 5;
    const int wm = wid & 1, wn = wid >> 1;      // 2 x 4 warp grid: warp tile 64x32
    const int g = lid >> 2, q = lid & 3;
    const int stsel = wid & 1;                  // substep-order stagger
    const int b = blockIdx.z, ntb = blockIdx.x, mtb = blockIdx.y;
    const int n0 = ntb * 128;
    const int m0 = (PHASE == 0 ? 0 : 1024) + mtb * 128;
    const __nv_bfloat16* Wp = g_wbf + (size_t)m0 * 1024;
    const __nv_bfloat16* Xp = g_xbf + ((size_t)b * HW_ + n0) * 1024;

    const int lrow = tid >> 1, lseg0 = (tid & 1) * 2;  // row 0..127, segs {0,1} or {2,3}

    float acc[4][4][4];
#pragma unroll
    for (int mt = 0; mt < 4; mt++)
#pragma unroll
        for (int nt = 0; nt < 4; nt++)
#pragma unroll
            for (int e = 0; e < 4; e++) acc[mt][nt][e] = 0.f;

    // ldmatrix lane address components
    const int alane = lid & 15;
    const int ahalf = (lid >> 4) << 3;
    const int brw = (lid & 7) + ((lid >> 4) << 3);
    const int bhalf = ((lid >> 3) & 1) << 3;
    uint32_t aob[4], bob[2];
#pragma unroll
    for (int mt = 0; mt < 4; mt++)
        aob[mt] = (uint32_t)((wm * 64 + mt * 16 + alane) * 40 + ahalf) * 2u;
#pragma unroll
    for (int p = 0; p < 2; p++)
        bob[p] = (uint32_t)((wn * 32 + p * 16 + brw) * 40 + bhalf) * 2u;

#define LOAD_STAGE(kb, sg)                                                                  \
    do {                                                                                    \
        _Pragma("unroll")                                                                   \
        for (int i_ = 0; i_ < 2; i_++) {                                                    \
            const int seg_ = lseg0 + i_;                                                    \
            cp16(sA + (uint32_t)(sg) * STG + (uint32_t)(lrow * 40 + seg_ * 8) * 2u,         \
                 Wp + (size_t)lrow * 1024 + (kb) * 32 + seg_ * 8);                          \
            cp16(sA + (uint32_t)(sg) * STG + 10240u + (uint32_t)(lrow * 40 + seg_ * 8) * 2u,\
                 Xp + (size_t)lrow * 1024 + (kb) * 32 + seg_ * 8);                          \
        }                                                                                   \
        CP_COMMIT();                                                                        \
    } while (0)

    LOAD_STAGE(0, 0);
    LOAD_STAGE(1, 1);
    LOAD_STAGE(2, 2);

    int cs = 0;      // consume stage (it % 5)
    int ls = 3;      // load stage ((it+3) % 5)
    for (int j = 0; j < 16; ++j) {
        // publish both stages of this window: all groups except the newest one done
        if (j < 15) { CP_WAIT(1); } else { CP_WAIT(0); }
        __syncthreads();
#pragma unroll
        for (int u = 0; u < 2; ++u) {
            const int it = 2 * j + u;
            const uint32_t Ac = sA + (uint32_t)cs * STG;
            const uint32_t Bc = Ac + 10240u;
#pragma unroll
            for (int s = 0; s < 2; s++) {
                const int st = s ^ stsel;       // odd warps: substep order 1,0
                uint32_t af[4][4], bfr[8];
#pragma unroll
                for (int mt = 0; mt < 4; mt++) ldsm4(af[mt], Ac + aob[mt] + st * 32);
#pragma unroll
                for (int p = 0; p < 2; p++) ldsm4(&bfr[p * 4], Bc + bob[p] + st * 32);
                if (s == 0 && it + 3 < 32) {
                    LOAD_STAGE(it + 3, ls);
                    ls = (ls == 4) ? 0 : ls + 1;
                }
#pragma unroll
                for (int mt = 0; mt < 4; mt++)
#pragma unroll
                    for (int nt = 0; nt < 4; nt++) {
                        const int bi = (nt >> 1) * 4 + (nt & 1) * 2;
                        mma16816(acc[mt][nt], af[mt][0], af[mt][1], af[mt][2], af[mt][3],
                                 bfr[bi], bfr[bi + 1]);
                    }
            }
            cs = (cs == 4) ? 0 : cs + 1;
        }
    }
    __syncthreads();
#undef LOAD_STAGE

    // ---------------- fused reduction epilogue ----------------
    if (PHASE == 0) {
        float* rowred = (float*)dsm;            // [128][4]
        float* mskS = (float*)dsm + 512;        // [128]
        const bool vrm = (mtb >= 4);
        if (vrm && tid < 128) mskS[tid] = g_mask[b * HW_ + n0 + tid];
        __syncthreads();
        float pr[4][2];
#pragma unroll
        for (int mt = 0; mt < 4; mt++) { pr[mt][0] = 0.f; pr[mt][1] = 0.f; }
#pragma unroll
        for (int mt = 0; mt < 4; mt++)
#pragma unroll
            for (int nt = 0; nt < 4; nt++)
#pragma unroll
                for (int rp = 0; rp < 2; rp++)
#pragma unroll
                    for (int e = 0; e < 2; e++) {
                        const float v = fmaxf(acc[mt][nt][rp * 2 + e], 0.f);
                        const int col = wn * 32 + nt * 8 + q * 2 + e;
                        pr[mt][rp] += vrm ? v * mskS[col] : v;
                    }
#pragma unroll
        for (int o = 1; o <= 2; o <<= 1)
#pragma unroll
            for (int mt = 0; mt < 4; mt++)
#pragma unroll
                for (int rp = 0; rp < 2; rp++)
                    pr[mt][rp] += __shfl_xor_sync(0xffffffffu, pr[mt][rp], o);
        if (q == 0) {
#pragma unroll
            for (int mt = 0; mt < 4; mt++)
#pragma unroll
                for (int rp = 0; rp < 2; rp++)
                    rowred[(wm * 64 + mt * 16 + g + rp * 8) * 4 + wn] = pr[mt][rp];
        }
        __syncthreads();
        if (tid < 128) {
            const float s = rowred[tid * 4] + rowred[tid * 4 + 1] +
                            rowred[tid * 4 + 2] + rowred[tid * 4 + 3];
            g_part_m[(((size_t)b * 8 + mtb) * 32 + ntb) * 128 + tid] = s;
        }
    } else {
        float* colred = (float*)dsm;            // [128][2]
        float* avS = (float*)dsm + 256;         // [128]
        if (tid < 128) avS[tid] = g_avg[b * CH_ + mtb * 128 + tid];
        __syncthreads();
        float pc[4][2];
#pragma unroll
        for (int nt = 0; nt < 4; nt++) { pc[nt][0] = 0.f; pc[nt][1] = 0.f; }
#pragma unroll
        for (int mt = 0; mt < 4; mt++)
#pragma unroll
            for (int rp = 0; rp < 2; rp++) {
                const float av = avS[wm * 64 + mt * 16 + g + rp * 8];
#pragma unroll
                for (int nt = 0; nt < 4; nt++)
#pragma unroll
                    for (int e = 0; e < 2; e++)
                        pc[nt][e] += av * fmaxf(acc[mt][nt][rp * 2 + e], 0.f);
            }
#pragma unroll
        for (int o = 4; o <= 16; o <<= 1)
#pragma unroll
            for (int nt = 0; nt < 4; nt++)
#pragma unroll
                for (int e = 0; e < 2; e++)
                    pc[nt][e] += __shfl_xor_sync(0xffffffffu, pc[nt][e], o);
        if (g == 0) {
#pragma unroll
            for (int nt = 0; nt < 4; nt++)
#pragma unroll
                for (int e = 0; e < 2; e++)
                    colred[(wn * 32 + nt * 8 + q * 2 + e) * 2 + wm] = pc[nt][e];
        }
        __syncthreads();
        if (tid < 128) {
            const float s = colred[tid * 2] + colred[tid * 2 + 1];
            g_part_n[(((size_t)b * 32 + ntb) * 4 + mtb) * 128 + tid] = s;
        }
    }
}

// deterministic reduce of part_n + sigmoid
__global__ void reduce_n2() {
    const int i = blockIdx.x * 256 + threadIdx.x;  // 65536
    const int b = i >> 12, n = i & 4095;
    const float* p = g_part_n + (((size_t)b * 32 + (n >> 7)) * 4) * 128 + (n & 127);
    const float s = p[0] + p[128] + p[256] + p[384];
    g_chattn[i] = 1.f / (1.f + __expf(-s));
}

// ---------------- final elementwise combine ----------------
__global__ void combine(const float* __restrict__ x, float* __restrict__ out) {
    const size_t i = (size_t)blockIdx.x * blockDim.x + threadIdx.x;
    const int n4 = (int)(i & 1023);
    const int c  = (int)((i >> 10) & 1023);
    const int b  = (int)(i >> 20);
    const float4 xv = ((const float4*)x)[i];
    const float4 ch = ((const float4*)g_chattn)[(size_t)b * 1024 + n4];
    const float sp = g_spatial[b * CH_ + (c & (CH_ - 1))];
    float4 o;
    if (c < CH_) {
        o.x = fmaf(xv.x, sp * ch.x, xv.x);
        o.y = fmaf(xv.y, sp * ch.y, xv.y);
        o.z = fmaf(xv.z, sp * ch.z, xv.z);
        o.w = fmaf(xv.w, sp * ch.w, xv.w);
    } else {
        o.x = fmaf(xv.x, sp + ch.x, xv.x);
        o.y = fmaf(xv.y, sp + ch.y, xv.y);
        o.z = fmaf(xv.z, sp + ch.z, xv.z);
        o.w = fmaf(xv.w, sp + ch.w, xv.w);
    }
    ((float4*)out)[i] = o;
}

// ---------------- launch ----------------
extern "C" void kernel_launch(void* const* d_in, const int* in_sizes, int n_in,
                              void* d_out, int out_size) {
    const float* x    = (const float*)d_in[0];
    const float* w_qr = (const float*)d_in[1];
    const float* w_vr = (const float*)d_in[2];
    const float* w_ql = (const float*)d_in[3];
    const float* w_vl = (const float*)d_in[4];
    float* out = (float*)d_out;

    cudaFuncSetAttribute(hmma_gemm<0>, cudaFuncAttributeMaxDynamicSharedMemorySize, SMEM_GEMM);
    cudaFuncSetAttribute(hmma_gemm<1>, cudaFuncAttributeMaxDynamicSharedMemorySize, SMEM_GEMM);

    convert_w<<<1536, 512>>>(w_ql, w_vr, w_vl);                        // 1
    transpose_x<<<dim3(HW_ / 32, C_ / 128, B_), 256>>>(x, w_qr);       // 2
    softmax_hw<<<B_, 1024>>>();                                        // 3
    hmma_gemm<0><<<dim3(32, 8, B_), 256, SMEM_GEMM>>>();               // 4  <- ncu target
    fuse_mid<<<B_, 512>>>();                                           // 5
    hmma_gemm<1><<<dim3(32, 4, B_), 256, SMEM_GEMM>>>();               // 6
    reduce_n2<<<256, 256>>>();                                         // 7
    combine<<<(B_ * C_ * HW_ / 4) / 256, 256>>>(x, out);               // 8
}

// round 13
// speedup vs baseline: 1.2223x; 1.0179x over previous
#include <cuda_runtime.h>
#include <cuda_bf16.h>
#include <stdint.h>
#include <math.h>

#define B_  16
#define C_  1024
#define CH_ 512
#define HW_ 4096

// ---------------- device scratch ----------------
__device__ __align__(16) __nv_bfloat16 g_wbf[1536 * 1024];              // stacked [ql;vr;vl] bf16
__device__ __align__(16) __nv_bfloat16 g_xbf[(size_t)B_ * HW_ * 1024];  // xT[b][n][k] bf16
__device__ __align__(16) float g_qrp[B_ * 8 * HW_];  // qr partials per 128-channel block
__device__ __align__(16) float g_mask[B_ * HW_];
__device__ __align__(16) float g_avg[B_ * CH_];
__device__ __align__(16) float g_spatial[B_ * CH_];
__device__ __align__(16) float g_chattn[B_ * HW_];
__device__ __align__(16) float g_part_m[B_ * 8 * 32 * 128];  // (b, mtile8, ntile32, row128)
__device__ __align__(16) float g_part_n[B_ * 32 * 4 * 128];  // (b, ntile32, mtile4, col128)

// ---------------- helpers ----------------
__device__ __forceinline__ uint32_t s2u(const void* p) {
    uint32_t a;
    asm("{ .reg .u64 t; cvta.to.shared.u64 t, %1; cvt.u32.u64 %0, t; }" : "=r"(a) : "l"(p));
    return a;
}
__device__ __forceinline__ void cp16(uint32_t dst, const void* src) {
    asm volatile("cp.async.cg.shared.global [%0], [%1], 16;" :: "r"(dst), "l"(src) : "memory");
}
#define CP_COMMIT() asm volatile("cp.async.commit_group;" ::: "memory")
#define CP_WAIT(n)  asm volatile("cp.async.wait_group %0;" :: "n"(n) : "memory")

__device__ __forceinline__ void ldsm4(uint32_t* r, uint32_t addr) {
    asm volatile("ldmatrix.sync.aligned.m8n8.x4.shared.b16 {%0,%1,%2,%3}, [%4];"
                 : "=r"(r[0]), "=r"(r[1]), "=r"(r[2]), "=r"(r[3]) : "r"(addr));
}

__device__ __forceinline__ void mma16816(float* d, uint32_t a0, uint32_t a1, uint32_t a2,
                                         uint32_t a3, uint32_t b0, uint32_t b1) {
    asm volatile(
        "mma.sync.aligned.m16n8k16.row.col.f32.bf16.bf16.f32 "
        "{%0,%1,%2,%3}, {%4,%5,%6,%7}, {%8,%9}, {%0,%1,%2,%3};"
        : "+f"(d[0]), "+f"(d[1]), "+f"(d[2]), "+f"(d[3])
        : "r"(a0), "r"(a1), "r"(a2), "r"(a3), "r"(b0), "r"(b1));
}

// ---------------- conversion kernels ----------------
__global__ void convert_w(const float* __restrict__ wql, const float* __restrict__ wvr,
                          const float* __restrict__ wvl) {
    const int i = blockIdx.x * 512 + threadIdx.x;  // 786432 pairs
    const int m = i >> 9;
    const int k = (i & 511) * 2;
    const float* src = (m < 512) ? (wql + (size_t)m * 1024)
                                 : ((m < 1024) ? (wvr + (size_t)(m - 512) * 1024)
                                               : (wvl + (size_t)(m - 1024) * 1024));
    __nv_bfloat162 h = __floats2bfloat162_rn(src[k], src[k + 1]);
    ((uint32_t*)g_wbf)[i] = *reinterpret_cast<uint32_t*>(&h);
}

// x[b][c][n] fp32 -> xT[b][n][c] bf16, plus fused partial qr dot product.
__global__ void transpose_x(const float* __restrict__ x, const float* __restrict__ wqr) {
    __shared__ float s[32][129];
    const int tid = threadIdx.x;
    const int n0 = blockIdx.x * 32, c0 = blockIdx.y * 128, b = blockIdx.z;
#pragma unroll
    for (int r = 0; r < 16; r++) {
        const int ci = (tid >> 5) + r * 8;
        const int ni = tid & 31;
        s[ni][ci] = x[((size_t)(b * C_ + c0 + ci)) * HW_ + n0 + ni];
    }
    __syncthreads();
#pragma unroll
    for (int r = 0; r < 8; r++) {
        const int ni = (tid >> 6) + r * 4;
        const int u = tid & 63;
        __nv_bfloat162 h = __floats2bfloat162_rn(s[ni][u * 2], s[ni][u * 2 + 1]);
        ((uint32_t*)g_xbf)[((size_t)(b * HW_ + n0 + ni)) * 512 + (c0 >> 1) + u] =
            *reinterpret_cast<uint32_t*>(&h);
    }
    {
        const int ni = tid >> 3, lg = tid & 7;
        float p = 0.f;
#pragma unroll
        for (int r = 0; r < 16; r++) {
            const int ci = lg * 16 + r;
            p = fmaf(wqr[c0 + ci], s[ni][ci], p);
        }
#pragma unroll
        for (int o = 1; o <= 4; o <<= 1) p += __shfl_xor_sync(0xffffffffu, p, o);
        if (lg == 0) g_qrp[((size_t)b * 8 + blockIdx.y) * HW_ + n0 + ni] = p;
    }
}

// ---------------- small reductions ----------------
template <int NW>
__device__ __forceinline__ float blockSum(float v, float* sh, float* bc) {
#pragma unroll
    for (int o = 16; o > 0; o >>= 1) v += __shfl_xor_sync(0xffffffffu, v, o);
    int t = threadIdx.x;
    if ((t & 31) == 0) sh[t >> 5] = v;
    __syncthreads();
    if (t < 32) {
        float w = (t < NW) ? sh[t] : 0.f;
#pragma unroll
        for (int o = 16; o > 0; o >>= 1) w += __shfl_xor_sync(0xffffffffu, w, o);
        if (t == 0) *bc = w;
    }
    __syncthreads();
    return *bc;
}
template <int NW>
__device__ __forceinline__ float blockMax(float v, float* sh, float* bc) {
#pragma unroll
    for (int o = 16; o > 0; o >>= 1) v = fmaxf(v, __shfl_xor_sync(0xffffffffu, v, o));
    int t = threadIdx.x;
    if ((t & 31) == 0) sh[t >> 5] = v;
    __syncthreads();
    if (t < 32) {
        float w = (t < NW) ? sh[t] : -3.4e38f;
#pragma unroll
        for (int o = 16; o > 0; o >>= 1) w = fmaxf(w, __shfl_xor_sync(0xffffffffu, w, o));
        if (t == 0) *bc = w;
    }
    __syncthreads();
    return *bc;
}

// sum qr partials -> relu -> softmax over hw
__global__ void softmax_hw() {
    __shared__ float sh[32];
    __shared__ float bc;
    const int b = blockIdx.x, t = threadIdx.x;
    float v[4];
#pragma unroll
    for (int j = 0; j < 4; j++) {
        const int n = t + j * 1024;
        float s = 0.f;
#pragma unroll
        for (int cb = 0; cb < 8; cb++) s += g_qrp[((size_t)b * 8 + cb) * HW_ + n];
        v[j] = fmaxf(s, 0.f);
    }
    float m = fmaxf(fmaxf(v[0], v[1]), fmaxf(v[2], v[3]));
    const float bm = blockMax<32>(m, sh, &bc);
    float e[4], s = 0.f;
#pragma unroll
    for (int j = 0; j < 4; j++) { e[j] = __expf(v[j] - bm); s += e[j]; }
    const float bs = blockSum<32>(s, sh, &bc);
    const float inv = 1.f / bs;
#pragma unroll
    for (int j = 0; j < 4; j++) g_mask[b * HW_ + t + j * 1024] = e[j] * inv;
}

// fused: reduce part_m -> gx/ctx -> softmax(avg) + layernorm+sigmoid(spatial)
__global__ void fuse_mid() {
    __shared__ float sh[16];
    __shared__ float bc;
    const int b = blockIdx.x, t = threadIdx.x;  // 512 threads
    float s0 = 0.f, s1 = 0.f;
    {
        const int m = t;
        const float* p = g_part_m + (((size_t)b * 8 + (m >> 7)) * 32) * 128 + (m & 127);
#pragma unroll
        for (int nt = 0; nt < 32; nt++) s0 += p[nt * 128];
    }
    {
        const int m = t + 512;
        const float* p = g_part_m + (((size_t)b * 8 + (m >> 7)) * 32) * 128 + (m & 127);
#pragma unroll
        for (int nt = 0; nt < 32; nt++) s1 += p[nt * 128];
    }
    const float v = s0 * (1.f / (float)HW_);
    const float bm = blockMax<16>(v, sh, &bc);
    const float e = __expf(v - bm);
    const float bs = blockSum<16>(e, sh, &bc);
    g_avg[b * CH_ + t] = e / bs;
    const float mean = blockSum<16>(s1, sh, &bc) * (1.f / (float)CH_);
    const float d = s1 - mean;
    const float var = blockSum<16>(d * d, sh, &bc) * (1.f / (float)CH_);
    const float z = d * rsqrtf(var + 1e-5f);
    g_spatial[b * CH_ + t] = 1.f / (1.f + __expf(-z));
}

// ---------------- HMMA GEMM with fused reduction epilogues ----------------
// Block tile M=128, N=128, K=32; 256 threads (8 warps, 2x4), warp tile 64x32.
// Operands in 64B rows (RS=32, no pad) with chunk swizzle: 16B chunk index
//   chunk' = chunk ^ ((row>>1) & 3)
// -> ldmatrix conflict-free (8 lanes tile all 32 banks), cp.async stores
// conflict-free, all addresses 16B aligned. Substep-1 address = substep-0
// address XOR 32 (chunk+2 == chunk^2 for chunk in {0,1}; base 64B-aligned).
// 6-stage pipeline (stage 16384B), __syncthreads every 3 iterations: window j
// consumes slots {3j..3j+2} mod 6, loads the opposite triple — disjoint under
// any intra-window drift. 2 CTAs/SM (smem 98304B + align, regs <=128).
#define SMEM_GEMM (98304 + 128)
#define STG 16384u

template <int PHASE>
__global__ __launch_bounds__(256, 2) void hmma_gemm() {
    extern __shared__ char dsm[];
    const uint32_t sA = (s2u(dsm) + 63u) & ~63u;   // 64B-aligned base; B at +8192 per stage

    const int tid = threadIdx.x, lid = tid & 31, wid = tid >> 5;
    const int wm = wid & 1, wn = wid >> 1;      // 2 x 4 warp grid: warp tile 64x32
    const int g = lid >> 2, q = lid & 3;
    const int stsel = wid & 1;                  // substep-order stagger
    const int b = blockIdx.z, ntb = blockIdx.x, mtb = blockIdx.y;
    const int n0 = ntb * 128;
    const int m0 = (PHASE == 0 ? 0 : 1024) + mtb * 128;
    const __nv_bfloat16* Wp = g_wbf + (size_t)m0 * 1024;
    const __nv_bfloat16* Xp = g_xbf + ((size_t)b * HW_ + n0) * 1024;

    const int lrow = tid >> 1, lseg0 = (tid & 1) * 2;  // row 0..127, chunks {0,1} or {2,3}
    const uint32_t lswz = ((uint32_t)(lrow >> 1) & 3u);

    float acc[4][4][4];
#pragma unroll
    for (int mt = 0; mt < 4; mt++)
#pragma unroll
        for (int nt = 0; nt < 4; nt++)
#pragma unroll
            for (int e = 0; e < 4; e++) acc[mt][nt][e] = 0.f;

    // ldmatrix lane addresses (substep 0; substep 1 = XOR 32)
    const int alane = lid & 15;
    const uint32_t ahalfc = (uint32_t)(lid >> 4);        // chunk 0/1
    const int brw = (lid & 7) + ((lid >> 4) << 3);
    const uint32_t bhalfc = (uint32_t)((lid >> 3) & 1);  // chunk 0/1
    uint32_t aob[4], bob[2];
#pragma unroll
    for (int mt = 0; mt < 4; mt++) {
        const uint32_t row = (uint32_t)(wm * 64 + mt * 16 + alane);
        aob[mt] = row * 64u + ((ahalfc ^ ((row >> 1) & 3u)) * 16u);
    }
#pragma unroll
    for (int p = 0; p < 2; p++) {
        const uint32_t row = (uint32_t)(wn * 32 + p * 16 + brw);
        bob[p] = row * 64u + ((bhalfc ^ ((row >> 1) & 3u)) * 16u);
    }

#define LOAD_STAGE(kb, sg)                                                                  \
    do {                                                                                    \
        _Pragma("unroll")                                                                   \
        for (int i_ = 0; i_ < 2; i_++) {                                                    \
            const uint32_t seg_ = (uint32_t)(lseg0 + i_);                                   \
            const uint32_t soff = (uint32_t)lrow * 64u + ((seg_ ^ lswz) * 16u);             \
            cp16(sA + (uint32_t)(sg) * STG + soff,                                          \
                 Wp + (size_t)lrow * 1024 + (kb) * 32 + seg_ * 8);                          \
            cp16(sA + (uint32_t)(sg) * STG + 8192u + soff,                                  \
                 Xp + (size_t)lrow * 1024 + (kb) * 32 + seg_ * 8);                          \
        }                                                                                   \
        CP_COMMIT();                                                                        \
    } while (0)

    // one iteration's compute on stage slot `slot`
#define CONSUME(slot)                                                                       \
    do {                                                                                    \
        const uint32_t Ac = sA + (uint32_t)(slot) * STG;                                    \
        const uint32_t Bc = Ac + 8192u;                                                     \
        _Pragma("unroll")                                                                   \
        for (int s_ = 0; s_ < 2; s_++) {                                                    \
            const uint32_t sx_ = (uint32_t)(s_ ^ stsel) * 32u;                              \
            uint32_t af[4][4], bfr[8];                                                      \
            _Pragma("unroll")                                                               \
            for (int mt = 0; mt < 4; mt++) ldsm4(af[mt], (Ac + aob[mt]) ^ sx_);             \
            _Pragma("unroll")                                                               \
            for (int p = 0; p < 2; p++) ldsm4(&bfr[p * 4], (Bc + bob[p]) ^ sx_);            \
            _Pragma("unroll")                                                               \
            for (int mt = 0; mt < 4; mt++)                                                  \
                _Pragma("unroll")                                                           \
                for (int nt = 0; nt < 4; nt++) {                                            \
                    const int bi = (nt >> 1) * 4 + (nt & 1) * 2;                            \
                    mma16816(acc[mt][nt], af[mt][0], af[mt][1], af[mt][2], af[mt][3],       \
                             bfr[bi], bfr[bi + 1]);                                         \
                }                                                                           \
        }                                                                                   \
    } while (0)

    LOAD_STAGE(0, 0);
    LOAD_STAGE(1, 1);
    LOAD_STAGE(2, 2);

    int cs = 0;                           // stage slot of current iteration (it mod 6)
    for (int j = 0; j < 10; ++j) {        // windows of 3 iterations: iters 3j..3j+2
        const int it0 = 3 * j;
        CP_WAIT(0);
        __syncthreads();
        // u = 0: prefetch two stages (it0+3, it0+4)
        if (it0 + 3 < 32) LOAD_STAGE(it0 + 3, (cs + 3) % 6);
        if (it0 + 4 < 32) LOAD_STAGE(it0 + 4, (cs + 4) % 6);
        CONSUME(cs);
        cs = (cs == 5) ? 0 : cs + 1;
        // u = 1: prefetch one stage (it0+5)
        if (it0 + 5 < 32) LOAD_STAGE(it0 + 5, (cs + 4) % 6);
        CONSUME(cs);
        cs = (cs == 5) ? 0 : cs + 1;
        // u = 2
        CONSUME(cs);
        cs = (cs == 5) ? 0 : cs + 1;
    }
    // final window: iterations 30, 31
    CP_WAIT(0);
    __syncthreads();
    CONSUME(cs);
    cs = (cs == 5) ? 0 : cs + 1;
    CONSUME(cs);
    __syncthreads();
#undef LOAD_STAGE
#undef CONSUME

    // ---------------- fused reduction epilogue ----------------
    if (PHASE == 0) {
        float* rowred = (float*)dsm;            // [128][4]
        float* mskS = (float*)dsm + 512;        // [128]
        const bool vrm = (mtb >= 4);
        if (vrm && tid < 128) mskS[tid] = g_mask[b * HW_ + n0 + tid];
        __syncthreads();
        float pr[4][2];
#pragma unroll
        for (int mt = 0; mt < 4; mt++) { pr[mt][0] = 0.f; pr[mt][1] = 0.f; }
#pragma unroll
        for (int mt = 0; mt < 4; mt++)
#pragma unroll
            for (int nt = 0; nt < 4; nt++)
#pragma unroll
                for (int rp = 0; rp < 2; rp++)
#pragma unroll
                    for (int e = 0; e < 2; e++) {
                        const float v = fmaxf(acc[mt][nt][rp * 2 + e], 0.f);
                        const int col = wn * 32 + nt * 8 + q * 2 + e;
                        pr[mt][rp] += vrm ? v * mskS[col] : v;
                    }
#pragma unroll
        for (int o = 1; o <= 2; o <<= 1)
#pragma unroll
            for (int mt = 0; mt < 4; mt++)
#pragma unroll
                for (int rp = 0; rp < 2; rp++)
                    pr[mt][rp] += __shfl_xor_sync(0xffffffffu, pr[mt][rp], o);
        if (q == 0) {
#pragma unroll
            for (int mt = 0; mt < 4; mt++)
#pragma unroll
                for (int rp = 0; rp < 2; rp++)
                    rowred[(wm * 64 + mt * 16 + g + rp * 8) * 4 + wn] = pr[mt][rp];
        }
        __syncthreads();
        if (tid < 128) {
            const float s = rowred[tid * 4] + rowred[tid * 4 + 1] +
                            rowred[tid * 4 + 2] + rowred[tid * 4 + 3];
            g_part_m[(((size_t)b * 8 + mtb) * 32 + ntb) * 128 + tid] = s;
        }
    } else {
        float* colred = (float*)dsm;            // [128][2]
        float* avS = (float*)dsm + 256;         // [128]
        if (tid < 128) avS[tid] = g_avg[b * CH_ + mtb * 128 + tid];
        __syncthreads();
        float pc[4][2];
#pragma unroll
        for (int nt = 0; nt < 4; nt++) { pc[nt][0] = 0.f; pc[nt][1] = 0.f; }
#pragma unroll
        for (int mt = 0; mt < 4; mt++)
#pragma unroll
            for (int rp = 0; rp < 2; rp++) {
                const float av = avS[wm * 64 + mt * 16 + g + rp * 8];
#pragma unroll
                for (int nt = 0; nt < 4; nt++)
#pragma unroll
                    for (int e = 0; e < 2; e++)
                        pc[nt][e] += av * fmaxf(acc[mt][nt][rp * 2 + e], 0.f);
            }
#pragma unroll
        for (int o = 4; o <= 16; o <<= 1)
#pragma unroll
            for (int nt = 0; nt < 4; nt++)
#pragma unroll
                for (int e = 0; e < 2; e++)
                    pc[nt][e] += __shfl_xor_sync(0xffffffffu, pc[nt][e], o);
        if (g == 0) {
#pragma unroll
            for (int nt = 0; nt < 4; nt++)
#pragma unroll
                for (int e = 0; e < 2; e++)
                    colred[(wn * 32 + nt * 8 + q * 2 + e) * 2 + wm] = pc[nt][e];
        }
        __syncthreads();
        if (tid < 128) {
            const float s = colred[tid * 2] + colred[tid * 2 + 1];
            g_part_n[(((size_t)b * 32 + ntb) * 4 + mtb) * 128 + tid] = s;
        }
    }
}

// deterministic reduce of part_n + sigmoid
__global__ void reduce_n2() {
    const int i = blockIdx.x * 256 + threadIdx.x;  // 65536
    const int b = i >> 12, n = i & 4095;
    const float* p = g_part_n + (((size_t)b * 32 + (n >> 7)) * 4) * 128 + (n & 127);
    const float s = p[0] + p[128] + p[256] + p[384];
    g_chattn[i] = 1.f / (1.f + __expf(-s));
}

// ---------------- final elementwise combine ----------------
__global__ void combine(const float* __restrict__ x, float* __restrict__ out) {
    const size_t i = (size_t)blockIdx.x * blockDim.x + threadIdx.x;
    const int n4 = (int)(i & 1023);
    const int c  = (int)((i >> 10) & 1023);
    const int b  = (int)(i >> 20);
    const float4 xv = ((const float4*)x)[i];
    const float4 ch = ((const float4*)g_chattn)[(size_t)b * 1024 + n4];
    const float sp = g_spatial[b * CH_ + (c & (CH_ - 1))];
    float4 o;
    if (c < CH_) {
        o.x = fmaf(xv.x, sp * ch.x, xv.x);
        o.y = fmaf(xv.y, sp * ch.y, xv.y);
        o.z = fmaf(xv.z, sp * ch.z, xv.z);
        o.w = fmaf(xv.w, sp * ch.w, xv.w);
    } else {
        o.x = fmaf(xv.x, sp + ch.x, xv.x);
        o.y = fmaf(xv.y, sp + ch.y, xv.y);
        o.z = fmaf(xv.z, sp + ch.z, xv.z);
        o.w = fmaf(xv.w, sp + ch.w, xv.w);
    }
    ((float4*)out)[i] = o;
}

// ---------------- launch ----------------
extern "C" void kernel_launch(void* const* d_in, const int* in_sizes, int n_in,
                              void* d_out, int out_size) {
    const float* x    = (const float*)d_in[0];
    const float* w_qr = (const float*)d_in[1];
    const float* w_vr = (const float*)d_in[2];
    const float* w_ql = (const float*)d_in[3];
    const float* w_vl = (const float*)d_in[4];
    float* out = (float*)d_out;

    cudaFuncSetAttribute(hmma_gemm<0>, cudaFuncAttributeMaxDynamicSharedMemorySize, SMEM_GEMM);
    cudaFuncSetAttribute(hmma_gemm<1>, cudaFuncAttributeMaxDynamicSharedMemorySize, SMEM_GEMM);

    convert_w<<<1536, 512>>>(w_ql, w_vr, w_vl);                        // 1
    transpose_x<<<dim3(HW_ / 32, C_ / 128, B_), 256>>>(x, w_qr);       // 2
    softmax_hw<<<B_, 1024>>>();                                        // 3
    hmma_gemm<0><<<dim3(32, 8, B_), 256, SMEM_GEMM>>>();               // 4  <- ncu target
    fuse_mid<<<B_, 512>>>();                                           // 5
    hmma_gemm<1><<<dim3(32, 4, B_), 256, SMEM_GEMM>>>();               // 6
    reduce_n2<<<256, 256>>>();                                         // 7
    combine<<<(B_ * C_ * HW_ / 4) / 256, 256>>>(x, out);               // 8
}

// round 14
// speedup vs baseline: 1.3932x; 1.1398x over previous
#include <cuda_runtime.h>
#include <cuda_bf16.h>
#include <stdint.h>
#include <math.h>

#define B_  16
#define C_  1024
#define CH_ 512
#define HW_ 4096

// ---------------- device scratch ----------------
__device__ __align__(16) __nv_bfloat16 g_wbf[1536 * 1024];              // stacked [ql;vr;vl] bf16
__device__ __align__(16) __nv_bfloat16 g_xbf[(size_t)B_ * HW_ * 1024];  // xT[b][n][k] bf16
__device__ __align__(16) float g_qrp[B_ * 8 * HW_];  // qr partials per 128-channel block
__device__ __align__(16) float g_mask[B_ * HW_];
__device__ __align__(16) float g_avg[B_ * CH_];
__device__ __align__(16) float g_spatial[B_ * CH_];
__device__ __align__(16) float g_chattn[B_ * HW_];
__device__ __align__(16) float g_part_m[B_ * 8 * 32 * 128];  // (b, mtile8, ntile32, row128)
__device__ __align__(16) float g_part_n[B_ * 32 * 4 * 128];  // (b, ntile32, mtile4, col128)

// ---------------- helpers ----------------
__device__ __forceinline__ uint32_t s2u(const void* p) {
    uint32_t a;
    asm("{ .reg .u64 t; cvta.to.shared.u64 t, %1; cvt.u32.u64 %0, t; }" : "=r"(a) : "l"(p));
    return a;
}
__device__ __forceinline__ void cp16(uint32_t dst, const void* src) {
    asm volatile("cp.async.cg.shared.global [%0], [%1], 16;" :: "r"(dst), "l"(src) : "memory");
}
#define MBAR_INIT(a, c) \
    asm volatile("mbarrier.init.shared.b64 [%0], %1;" :: "r"(a), "r"(c) : "memory")
#define CPA_ARRIVE(a) \
    asm volatile("cp.async.mbarrier.arrive.noinc.shared.b64 [%0];" :: "r"(a) : "memory")
#define MBAR_ARRIVE(a) \
    asm volatile("mbarrier.arrive.shared.b64 _, [%0];" :: "r"(a) : "memory")

// lane-0 polls the mbarrier phase, then the warp syncs.
__device__ __forceinline__ void mwait(uint32_t addr, uint32_t parity, int lid) {
    if (lid == 0) {
        uint32_t done = 0;
        while (!done) {
            asm volatile(
                "{\n\t.reg .pred p;\n\t"
                "mbarrier.try_wait.parity.acquire.cta.shared::cta.b64 p, [%1], %2, 0x989680;\n\t"
                "selp.b32 %0, 1, 0, p;\n\t}"
                : "=r"(done) : "r"(addr), "r"(parity) : "memory");
        }
    }
    __syncwarp();
}

__device__ __forceinline__ void ldsm4(uint32_t* r, uint32_t addr) {
    asm volatile("ldmatrix.sync.aligned.m8n8.x4.shared.b16 {%0,%1,%2,%3}, [%4];"
                 : "=r"(r[0]), "=r"(r[1]), "=r"(r[2]), "=r"(r[3]) : "r"(addr));
}

__device__ __forceinline__ void mma16816(float* d, uint32_t a0, uint32_t a1, uint32_t a2,
                                         uint32_t a3, uint32_t b0, uint32_t b1) {
    asm volatile(
        "mma.sync.aligned.m16n8k16.row.col.f32.bf16.bf16.f32 "
        "{%0,%1,%2,%3}, {%4,%5,%6,%7}, {%8,%9}, {%0,%1,%2,%3};"
        : "+f"(d[0]), "+f"(d[1]), "+f"(d[2]), "+f"(d[3])
        : "r"(a0), "r"(a1), "r"(a2), "r"(a3), "r"(b0), "r"(b1));
}

// ---------------- conversion kernels ----------------
__global__ void convert_w(const float* __restrict__ wql, const float* __restrict__ wvr,
                          const float* __restrict__ wvl) {
    const int i = blockIdx.x * 512 + threadIdx.x;  // 786432 pairs
    const int m = i >> 9;
    const int k = (i & 511) * 2;
    const float* src = (m < 512) ? (wql + (size_t)m * 1024)
                                 : ((m < 1024) ? (wvr + (size_t)(m - 512) * 1024)
                                               : (wvl + (size_t)(m - 1024) * 1024));
    __nv_bfloat162 h = __floats2bfloat162_rn(src[k], src[k + 1]);
    ((uint32_t*)g_wbf)[i] = *reinterpret_cast<uint32_t*>(&h);
}

// x[b][c][n] fp32 -> xT[b][n][c] bf16, plus fused partial qr dot product.
__global__ void transpose_x(const float* __restrict__ x, const float* __restrict__ wqr) {
    __shared__ float s[32][129];
    const int tid = threadIdx.x;
    const int n0 = blockIdx.x * 32, c0 = blockIdx.y * 128, b = blockIdx.z;
#pragma unroll
    for (int r = 0; r < 16; r++) {
        const int ci = (tid >> 5) + r * 8;
        const int ni = tid & 31;
        s[ni][ci] = x[((size_t)(b * C_ + c0 + ci)) * HW_ + n0 + ni];
    }
    __syncthreads();
#pragma unroll
    for (int r = 0; r < 8; r++) {
        const int ni = (tid >> 6) + r * 4;
        const int u = tid & 63;
        __nv_bfloat162 h = __floats2bfloat162_rn(s[ni][u * 2], s[ni][u * 2 + 1]);
        ((uint32_t*)g_xbf)[((size_t)(b * HW_ + n0 + ni)) * 512 + (c0 >> 1) + u] =
            *reinterpret_cast<uint32_t*>(&h);
    }
    {
        const int ni = tid >> 3, lg = tid & 7;
        float p = 0.f;
#pragma unroll
        for (int r = 0; r < 16; r++) {
            const int ci = lg * 16 + r;
            p = fmaf(wqr[c0 + ci], s[ni][ci], p);
        }
#pragma unroll
        for (int o = 1; o <= 4; o <<= 1) p += __shfl_xor_sync(0xffffffffu, p, o);
        if (lg == 0) g_qrp[((size_t)b * 8 + blockIdx.y) * HW_ + n0 + ni] = p;
    }
}

// ---------------- small reductions ----------------
template <int NW>
__device__ __forceinline__ float blockSum(float v, float* sh, float* bc) {
#pragma unroll
    for (int o = 16; o > 0; o >>= 1) v += __shfl_xor_sync(0xffffffffu, v, o);
    int t = threadIdx.x;
    if ((t & 31) == 0) sh[t >> 5] = v;
    __syncthreads();
    if (t < 32) {
        float w = (t < NW) ? sh[t] : 0.f;
#pragma unroll
        for (int o = 16; o > 0; o >>= 1) w += __shfl_xor_sync(0xffffffffu, w, o);
        if (t == 0) *bc = w;
    }
    __syncthreads();
    return *bc;
}
template <int NW>
__device__ __forceinline__ float blockMax(float v, float* sh, float* bc) {
#pragma unroll
    for (int o = 16; o > 0; o >>= 1) v = fmaxf(v, __shfl_xor_sync(0xffffffffu, v, o));
    int t = threadIdx.x;
    if ((t & 31) == 0) sh[t >> 5] = v;
    __syncthreads();
    if (t < 32) {
        float w = (t < NW) ? sh[t] : -3.4e38f;
#pragma unroll
        for (int o = 16; o > 0; o >>= 1) w = fmaxf(w, __shfl_xor_sync(0xffffffffu, w, o));
        if (t == 0) *bc = w;
    }
    __syncthreads();
    return *bc;
}

// sum qr partials -> relu -> softmax over hw
__global__ void softmax_hw() {
    __shared__ float sh[32];
    __shared__ float bc;
    const int b = blockIdx.x, t = threadIdx.x;
    float v[4];
#pragma unroll
    for (int j = 0; j < 4; j++) {
        const int n = t + j * 1024;
        float s = 0.f;
#pragma unroll
        for (int cb = 0; cb < 8; cb++) s += g_qrp[((size_t)b * 8 + cb) * HW_ + n];
        v[j] = fmaxf(s, 0.f);
    }
    float m = fmaxf(fmaxf(v[0], v[1]), fmaxf(v[2], v[3]));
    const float bm = blockMax<32>(m, sh, &bc);
    float e[4], s = 0.f;
#pragma unroll
    for (int j = 0; j < 4; j++) { e[j] = __expf(v[j] - bm); s += e[j]; }
    const float bs = blockSum<32>(s, sh, &bc);
    const float inv = 1.f / bs;
#pragma unroll
    for (int j = 0; j < 4; j++) g_mask[b * HW_ + t + j * 1024] = e[j] * inv;
}

// fused: reduce part_m -> gx/ctx -> softmax(avg) + layernorm+sigmoid(spatial)
__global__ void fuse_mid() {
    __shared__ float sh[16];
    __shared__ float bc;
    const int b = blockIdx.x, t = threadIdx.x;  // 512 threads
    float s0 = 0.f, s1 = 0.f;
    {
        const int m = t;
        const float* p = g_part_m + (((size_t)b * 8 + (m >> 7)) * 32) * 128 + (m & 127);
#pragma unroll
        for (int nt = 0; nt < 32; nt++) s0 += p[nt * 128];
    }
    {
        const int m = t + 512;
        const float* p = g_part_m + (((size_t)b * 8 + (m >> 7)) * 32) * 128 + (m & 127);
#pragma unroll
        for (int nt = 0; nt < 32; nt++) s1 += p[nt * 128];
    }
    const float v = s0 * (1.f / (float)HW_);
    const float bm = blockMax<16>(v, sh, &bc);
    const float e = __expf(v - bm);
    const float bs = blockSum<16>(e, sh, &bc);
    g_avg[b * CH_ + t] = e / bs;
    const float mean = blockSum<16>(s1, sh, &bc) * (1.f / (float)CH_);
    const float d = s1 - mean;
    const float var = blockSum<16>(d * d, sh, &bc) * (1.f / (float)CH_);
    const float z = d * rsqrtf(var + 1e-5f);
    g_spatial[b * CH_ + t] = 1.f / (1.f + __expf(-z));
}

// ---------------- HMMA GEMM with fused reduction epilogues ----------------
// Block tile M=128, N=128, K=32; 256 threads (8 warps, 2x4), warp tile 64x32.
// Chunk-swizzled 64B-row layout (conflict-free ldsm + cp.async, see R13).
// NEW: NO __syncthreads in the mainloop. 6-slot ring with per-slot mbarriers:
//   full[s]  (count 256): cp.async.mbarrier.arrive.noinc per thread — fires
//            asynchronously when the stage data LANDS, decoupled from warp PC.
//   empty[s] (count 8):   lane-0 per warp arrives after consuming the slot.
// Producer at iter `it` loads stage it+3 and (pass>0) waits empty of the pass
// consumed at it-3 -> warps free-run with drift <= 3 iterations.
// 2 CTAs/SM (smem 98560B/CTA, regs <=128).
#define SMEM_GEMM 98560
#define STG 16384u

template <int PHASE>
__global__ __launch_bounds__(256, 2) void hmma_gemm() {
    extern __shared__ char dsm[];
    const uint32_t base = (s2u(dsm) + 63u) & ~63u;
    const uint32_t mbF = base;            // full[0..5]  at +0..47
    const uint32_t mbE = base + 48u;      // empty[0..5] at +48..95
    const uint32_t sA = base + 128u;      // stages: A at slot*STG, B at +8192

    const int tid = threadIdx.x, lid = tid & 31, wid = tid >> 5;
    const int wm = wid & 1, wn = wid >> 1;      // 2 x 4 warp grid: warp tile 64x32
    const int g = lid >> 2, q = lid & 3;
    const int stsel = wid & 1;                  // substep-order stagger
    const int b = blockIdx.z, ntb = blockIdx.x, mtb = blockIdx.y;
    const int n0 = ntb * 128;
    const int m0 = (PHASE == 0 ? 0 : 1024) + mtb * 128;
    const __nv_bfloat16* Wp = g_wbf + (size_t)m0 * 1024;
    const __nv_bfloat16* Xp = g_xbf + ((size_t)b * HW_ + n0) * 1024;

    const int lrow = tid >> 1, lseg0 = (tid & 1) * 2;  // row 0..127, chunks {0,1} or {2,3}
    const uint32_t lswz = ((uint32_t)(lrow >> 1) & 3u);

    float acc[4][4][4];
#pragma unroll
    for (int mt = 0; mt < 4; mt++)
#pragma unroll
        for (int nt = 0; nt < 4; nt++)
#pragma unroll
            for (int e = 0; e < 4; e++) acc[mt][nt][e] = 0.f;

    // ldmatrix lane addresses (substep 0; substep 1 = XOR 32)
    const int alane = lid & 15;
    const uint32_t ahalfc = (uint32_t)(lid >> 4);
    const int brw = (lid & 7) + ((lid >> 4) << 3);
    const uint32_t bhalfc = (uint32_t)((lid >> 3) & 1);
    uint32_t aob[4], bob[2];
#pragma unroll
    for (int mt = 0; mt < 4; mt++) {
        const uint32_t row = (uint32_t)(wm * 64 + mt * 16 + alane);
        aob[mt] = row * 64u + ((ahalfc ^ ((row >> 1) & 3u)) * 16u);
    }
#pragma unroll
    for (int p = 0; p < 2; p++) {
        const uint32_t row = (uint32_t)(wn * 32 + p * 16 + brw);
        bob[p] = row * 64u + ((bhalfc ^ ((row >> 1) & 3u)) * 16u);
    }

    // stage load: 4 cp.async per thread, then async arrive on full[slot]
#define LOAD_STAGE(kb, sg)                                                                  \
    do {                                                                                    \
        _Pragma("unroll")                                                                   \
        for (int i_ = 0; i_ < 2; i_++) {                                                    \
            const uint32_t seg_ = (uint32_t)(lseg0 + i_);                                   \
            const uint32_t soff = (uint32_t)lrow * 64u + ((seg_ ^ lswz) * 16u);             \
            cp16(sA + (uint32_t)(sg) * STG + soff,                                          \
                 Wp + (size_t)lrow * 1024 + (kb) * 32 + seg_ * 8);                          \
            cp16(sA + (uint32_t)(sg) * STG + 8192u + soff,                                  \
                 Xp + (size_t)lrow * 1024 + (kb) * 32 + seg_ * 8);                          \
        }                                                                                   \
        CPA_ARRIVE(mbF + (uint32_t)(sg) * 8u);                                              \
    } while (0)

#define CONSUME(slot)                                                                       \
    do {                                                                                    \
        const uint32_t Ac = sA + (uint32_t)(slot) * STG;                                    \
        const uint32_t Bc = Ac + 8192u;                                                     \
        _Pragma("unroll")                                                                   \
        for (int s_ = 0; s_ < 2; s_++) {                                                    \
            const uint32_t sx_ = (uint32_t)(s_ ^ stsel) * 32u;                              \
            uint32_t af[4][4], bfr[8];                                                      \
            _Pragma("unroll")                                                               \
            for (int mt = 0; mt < 4; mt++) ldsm4(af[mt], (Ac + aob[mt]) ^ sx_);             \
            _Pragma("unroll")                                                               \
            for (int p = 0; p < 2; p++) ldsm4(&bfr[p * 4], (Bc + bob[p]) ^ sx_);            \
            _Pragma("unroll")                                                               \
            for (int mt = 0; mt < 4; mt++)                                                  \
                _Pragma("unroll")                                                           \
                for (int nt = 0; nt < 4; nt++) {                                            \
                    const int bi = (nt >> 1) * 4 + (nt & 1) * 2;                            \
                    mma16816(acc[mt][nt], af[mt][0], af[mt][1], af[mt][2], af[mt][3],       \
                             bfr[bi], bfr[bi + 1]);                                         \
                }                                                                           \
        }                                                                                   \
    } while (0)

    if (tid == 0) {
#pragma unroll
        for (int s2 = 0; s2 < 6; s2++) {
            MBAR_INIT(mbF + (uint32_t)s2 * 8u, 256);
            MBAR_INIT(mbE + (uint32_t)s2 * 8u, 8);
        }
    }
    __syncthreads();

    // prologue: prefetch 3 stages
    LOAD_STAGE(0, 0);
    LOAD_STAGE(1, 1);
    LOAD_STAGE(2, 2);

    int cs = 0;
    for (int it = 0; it < 32; ++it) {
        // producer: load stage it+3 into slot (it+3)%6
        if (it + 3 < 32) {
            const int sl = (it + 3) % 6;
            const int pp = (it + 3) / 6;
            if (pp > 0) mwait(mbE + (uint32_t)sl * 8u, (uint32_t)((pp - 1) & 1), lid);
            LOAD_STAGE(it + 3, sl);
        }
        // consumer: wait data-landed, consume, release slot
        mwait(mbF + (uint32_t)cs * 8u, (uint32_t)((it / 6) & 1), lid);
        CONSUME(cs);
        __syncwarp();
        if (lid == 0) MBAR_ARRIVE(mbE + (uint32_t)cs * 8u);
        cs = (cs == 5) ? 0 : cs + 1;
    }
    __syncthreads();
#undef LOAD_STAGE
#undef CONSUME

    // ---------------- fused reduction epilogue ----------------
    if (PHASE == 0) {
        float* rowred = (float*)dsm;            // [128][4]
        float* mskS = (float*)dsm + 512;        // [128]
        const bool vrm = (mtb >= 4);
        if (vrm && tid < 128) mskS[tid] = g_mask[b * HW_ + n0 + tid];
        __syncthreads();
        float pr[4][2];
#pragma unroll
        for (int mt = 0; mt < 4; mt++) { pr[mt][0] = 0.f; pr[mt][1] = 0.f; }
#pragma unroll
        for (int mt = 0; mt < 4; mt++)
#pragma unroll
            for (int nt = 0; nt < 4; nt++)
#pragma unroll
                for (int rp = 0; rp < 2; rp++)
#pragma unroll
                    for (int e = 0; e < 2; e++) {
                        const float v = fmaxf(acc[mt][nt][rp * 2 + e], 0.f);
                        const int col = wn * 32 + nt * 8 + q * 2 + e;
                        pr[mt][rp] += vrm ? v * mskS[col] : v;
                    }
#pragma unroll
        for (int o = 1; o <= 2; o <<= 1)
#pragma unroll
            for (int mt = 0; mt < 4; mt++)
#pragma unroll
                for (int rp = 0; rp < 2; rp++)
                    pr[mt][rp] += __shfl_xor_sync(0xffffffffu, pr[mt][rp], o);
        if (q == 0) {
#pragma unroll
            for (int mt = 0; mt < 4; mt++)
#pragma unroll
                for (int rp = 0; rp < 2; rp++)
                    rowred[(wm * 64 + mt * 16 + g + rp * 8) * 4 + wn] = pr[mt][rp];
        }
        __syncthreads();
        if (tid < 128) {
            const float s = rowred[tid * 4] + rowred[tid * 4 + 1] +
                            rowred[tid * 4 + 2] + rowred[tid * 4 + 3];
            g_part_m[(((size_t)b * 8 + mtb) * 32 + ntb) * 128 + tid] = s;
        }
    } else {
        float* colred = (float*)dsm;            // [128][2]
        float* avS = (float*)dsm + 256;         // [128]
        if (tid < 128) avS[tid] = g_avg[b * CH_ + mtb * 128 + tid];
        __syncthreads();
        float pc[4][2];
#pragma unroll
        for (int nt = 0; nt < 4; nt++) { pc[nt][0] = 0.f; pc[nt][1] = 0.f; }
#pragma unroll
        for (int mt = 0; mt < 4; mt++)
#pragma unroll
            for (int rp = 0; rp < 2; rp++) {
                const float av = avS[wm * 64 + mt * 16 + g + rp * 8];
#pragma unroll
                for (int nt = 0; nt < 4; nt++)
#pragma unroll
                    for (int e = 0; e < 2; e++)
                        pc[nt][e] += av * fmaxf(acc[mt][nt][rp * 2 + e], 0.f);
            }
#pragma unroll
        for (int o = 4; o <= 16; o <<= 1)
#pragma unroll
            for (int nt = 0; nt < 4; nt++)
#pragma unroll
                for (int e = 0; e < 2; e++)
                    pc[nt][e] += __shfl_xor_sync(0xffffffffu, pc[nt][e], o);
        if (g == 0) {
#pragma unroll
            for (int nt = 0; nt < 4; nt++)
#pragma unroll
                for (int e = 0; e < 2; e++)
                    colred[(wn * 32 + nt * 8 + q * 2 + e) * 2 + wm] = pc[nt][e];
        }
        __syncthreads();
        if (tid < 128) {
            const float s = colred[tid * 2] + colred[tid * 2 + 1];
            g_part_n[(((size_t)b * 32 + ntb) * 4 + mtb) * 128 + tid] = s;
        }
    }
}

// deterministic reduce of part_n + sigmoid
__global__ void reduce_n2() {
    const int i = blockIdx.x * 256 + threadIdx.x;  // 65536
    const int b = i >> 12, n = i & 4095;
    const float* p = g_part_n + (((size_t)b * 32 + (n >> 7)) * 4) * 128 + (n & 127);
    const float s = p[0] + p[128] + p[256] + p[384];
    g_chattn[i] = 1.f / (1.f + __expf(-s));
}

// ---------------- final elementwise combine ----------------
__global__ void combine(const float* __restrict__ x, float* __restrict__ out) {
    const size_t i = (size_t)blockIdx.x * blockDim.x + threadIdx.x;
    const int n4 = (int)(i & 1023);
    const int c  = (int)((i >> 10) & 1023);
    const int b  = (int)(i >> 20);
    const float4 xv = ((const float4*)x)[i];
    const float4 ch = ((const float4*)g_chattn)[(size_t)b * 1024 + n4];
    const float sp = g_spatial[b * CH_ + (c & (CH_ - 1))];
    float4 o;
    if (c < CH_) {
        o.x = fmaf(xv.x, sp * ch.x, xv.x);
        o.y = fmaf(xv.y, sp * ch.y, xv.y);
        o.z = fmaf(xv.z, sp * ch.z, xv.z);
        o.w = fmaf(xv.w, sp * ch.w, xv.w);
    } else {
        o.x = fmaf(xv.x, sp + ch.x, xv.x);
        o.y = fmaf(xv.y, sp + ch.y, xv.y);
        o.z = fmaf(xv.z, sp + ch.z, xv.z);
        o.w = fmaf(xv.w, sp + ch.w, xv.w);
    }
    ((float4*)out)[i] = o;
}

// ---------------- launch ----------------
extern "C" void kernel_launch(void* const* d_in, const int* in_sizes, int n_in,
                              void* d_out, int out_size) {
    const float* x    = (const float*)d_in[0];
    const float* w_qr = (const float*)d_in[1];
    const float* w_vr = (const float*)d_in[2];
    const float* w_ql = (const float*)d_in[3];
    const float* w_vl = (const float*)d_in[4];
    float* out = (float*)d_out;

    cudaFuncSetAttribute(hmma_gemm<0>, cudaFuncAttributeMaxDynamicSharedMemorySize, SMEM_GEMM);
    cudaFuncSetAttribute(hmma_gemm<1>, cudaFuncAttributeMaxDynamicSharedMemorySize, SMEM_GEMM);

    convert_w<<<1536, 512>>>(w_ql, w_vr, w_vl);                        // 1
    transpose_x<<<dim3(HW_ / 32, C_ / 128, B_), 256>>>(x, w_qr);       // 2
    softmax_hw<<<B_, 1024>>>();                                        // 3
    hmma_gemm<0><<<dim3(32, 8, B_), 256, SMEM_GEMM>>>();               // 4  <- ncu target
    fuse_mid<<<B_, 512>>>();                                           // 5
    hmma_gemm<1><<<dim3(32, 4, B_), 256, SMEM_GEMM>>>();               // 6
    reduce_n2<<<256, 256>>>();                                         // 7
    combine<<<(B_ * C_ * HW_ / 4) / 256, 256>>>(x, out);               // 8
}